// round 1
// baseline (speedup 1.0000x reference)
#include <cuda_runtime.h>
#include <cstddef>

// ---------------- problem constants ----------------
#define TT   4
#define BB   8
#define CC   512
#define VV   1024
#define HID  2048
#define NH   8
#define DH   64          // head dim
#define NTB  (TT*BB)     // 32 batched GEMM slices
#define NPER (BB*CC*VV)          // elements per timestep (C=512): 4,194,304
#define NPERH (BB*HID*VV)        // elements per timestep (H=2048): 16,777,216
#define MAIN_ELEMS (TT*BB*CC*VV) // 16,777,216

// ---------------- scratch (device globals; no allocation allowed) ----------------
__device__ float g_xs[MAIN_ELEMS];
__device__ float g_zq[MAIN_ELEMS];
__device__ float g_zk[MAIN_ELEMS];
__device__ float g_zv[MAIN_ELEMS];
__device__ float g_y [MAIN_ELEMS];
__device__ float g_xattn[MAIN_ELEMS];
__device__ float g_m1[MAIN_ELEMS];
__device__ float g_hid[TT*BB*HID*VV];   // 67,108,864 floats

// ---------------- LIF: multi-step leaky integrate & fire, tau=2, hard reset ----------------
// h = v + (x - v)/2 ; s = (h >= vth) ; v' = s ? 0 : h
__global__ void lif4_kernel(const float* __restrict__ x, float* __restrict__ s,
                            float vth, int nper)
{
    int i = (blockIdx.x * blockDim.x + threadIdx.x) * 4;
    if (i >= nper) return;
    float4 v = make_float4(0.f, 0.f, 0.f, 0.f);
#pragma unroll
    for (int t = 0; t < TT; t++) {
        float4 xt = *(const float4*)(x + (size_t)t * nper + i);
        float4 h, sp;
        h.x = v.x + (xt.x - v.x) * 0.5f;
        h.y = v.y + (xt.y - v.y) * 0.5f;
        h.z = v.z + (xt.z - v.z) * 0.5f;
        h.w = v.w + (xt.w - v.w) * 0.5f;
        sp.x = (h.x >= vth) ? 1.f : 0.f;
        sp.y = (h.y >= vth) ? 1.f : 0.f;
        sp.z = (h.z >= vth) ? 1.f : 0.f;
        sp.w = (h.w >= vth) ? 1.f : 0.f;
        v.x = (sp.x > 0.f) ? 0.f : h.x;
        v.y = (sp.y > 0.f) ? 0.f : h.y;
        v.z = (sp.z > 0.f) ? 0.f : h.z;
        v.w = (sp.w > 0.f) ? 0.f : h.w;
        *(float4*)(s + (size_t)t * nper + i) = sp;
    }
}

// ---------------- batched GEMM + fused epilogue ----------------
// For each batch slice: Y[m,n] = (sum_k W[m,k]*X[k,n] + cb[m]) * sc[m] + bb[m] (+ res[m,n])
// W: [M,K] row-major. X: batch stride K*N. Y: batch stride M*N.
// BM=BN=128, BK=8, 256 threads, 8x8 microtile.
__global__ __launch_bounds__(256)
void gemm_epi_kernel(const float* __restrict__ W, const float* __restrict__ X,
                     float* __restrict__ Y,
                     const float* __restrict__ cb, const float* __restrict__ sc,
                     const float* __restrict__ bb, const float* __restrict__ res,
                     int M, int N, int K)
{
    int batch = blockIdx.z;
    const float* Xb = X + (size_t)batch * K * N;
    float*       Yb = Y + (size_t)batch * M * N;
    const float* Rb = res ? (res + (size_t)batch * M * N) : nullptr;

    __shared__ float As[8][128];
    __shared__ float Bs[8][128];

    int tid  = threadIdx.x;
    int bm   = blockIdx.y << 7;
    int bn   = blockIdx.x << 7;
    int arow = tid >> 1, acol = (tid & 1) << 2;
    int brow = tid >> 5, bcol = (tid & 31) << 2;
    const float* Ap = W  + (size_t)(bm + arow) * K + acol;
    const float* Bp = Xb + (size_t)brow * N + bn + bcol;

    float acc[8][8];
#pragma unroll
    for (int i = 0; i < 8; i++)
#pragma unroll
        for (int j = 0; j < 8; j++) acc[i][j] = 0.f;

    int tx = tid & 15, ty = tid >> 4;

    for (int k0 = 0; k0 < K; k0 += 8) {
        float4 a  = *(const float4*)(Ap + k0);
        float4 bv = *(const float4*)(Bp + (size_t)k0 * N);
        As[acol + 0][arow] = a.x;
        As[acol + 1][arow] = a.y;
        As[acol + 2][arow] = a.z;
        As[acol + 3][arow] = a.w;
        *(float4*)(&Bs[brow][bcol]) = bv;
        __syncthreads();
#pragma unroll
        for (int kk = 0; kk < 8; kk++) {
            float ra[8], rb[8];
#pragma unroll
            for (int i = 0; i < 8; i++) ra[i] = As[kk][(ty << 3) + i];
#pragma unroll
            for (int j = 0; j < 8; j++) rb[j] = Bs[kk][(tx << 3) + j];
#pragma unroll
            for (int i = 0; i < 8; i++)
#pragma unroll
                for (int j = 0; j < 8; j++)
                    acc[i][j] = fmaf(ra[i], rb[j], acc[i][j]);
        }
        __syncthreads();
    }

#pragma unroll
    for (int i = 0; i < 8; i++) {
        int m = bm + (ty << 3) + i;
        float c  = cb ? cb[m] : 0.f;
        float s  = sc[m];
        float b2 = bb[m];
        size_t rowoff = (size_t)m * N + bn + (tx << 3);
#pragma unroll
        for (int j = 0; j < 8; j++) {
            float val = (acc[i][j] + c) * s + b2;
            if (Rb) val += Rb[rowoff + j];
            Yb[rowoff + j] = val;
        }
    }
}

// ---------------- chunked linear attention ----------------
// Per (n_, b, h): attn[d,e] = (1/1024) * sum_{l<2048} K[l,d]*V[l,e];
// out[l,e] = sum_d Q[l,d]*attn[d,e] -> y[t, b, h*64+e, nn]
// l = c_idx*1024 + nn, t = 2*n_ + c_idx.  256 threads per block.
__global__ __launch_bounds__(256)
void attn_kernel(const float* __restrict__ q, const float* __restrict__ k,
                 const float* __restrict__ v, float* __restrict__ y)
{
    int idx = blockIdx.x;
    int h = idx & 7, b = (idx >> 3) & 7, n_ = idx >> 6;

    __shared__ float Ks[64][65];     // [l][d] tile (also reused for Q)
    __shared__ float Vs[64][64];     // [l][e] tile; reused as Atn[d][e] in phase 2
    float* Atn = &Vs[0][0];

    int tid = threadIdx.x;
    int ldd = tid >> 2;              // channel index (d or e) 0..63
    int llb = (tid & 3) << 4;        // l offset within tile, 16 per thread

    int dd0 = (tid >> 4) << 2;       // phase-1 ownership: 4x4 tile of (d,e)
    int ee0 = (tid & 15) << 2;

    float acc[4][4];
#pragma unroll
    for (int i = 0; i < 4; i++)
#pragma unroll
        for (int j = 0; j < 4; j++) acc[i][j] = 0.f;

    // ---- phase 1: attn = K^T V (sum over l = 2048) ----
    for (int l0 = 0; l0 < 2048; l0 += 64) {
        int t   = (n_ << 1) + (l0 >> 10);
        int nn0 = l0 & 1023;
        size_t base = ((size_t)(t * BB + b) * CC + h * DH + ldd) * VV + nn0 + llb;
#pragma unroll
        for (int u = 0; u < 16; u += 4) {
            float4 k4 = *(const float4*)(k + base + u);
            Ks[llb + u + 0][ldd] = k4.x;
            Ks[llb + u + 1][ldd] = k4.y;
            Ks[llb + u + 2][ldd] = k4.z;
            Ks[llb + u + 3][ldd] = k4.w;
            float4 v4 = *(const float4*)(v + base + u);
            Vs[llb + u + 0][ldd] = v4.x;
            Vs[llb + u + 1][ldd] = v4.y;
            Vs[llb + u + 2][ldd] = v4.z;
            Vs[llb + u + 3][ldd] = v4.w;
        }
        __syncthreads();
#pragma unroll 4
        for (int ll = 0; ll < 64; ll++) {
            float ka[4], vb[4];
#pragma unroll
            for (int i = 0; i < 4; i++) ka[i] = Ks[ll][dd0 + i];
#pragma unroll
            for (int j = 0; j < 4; j++) vb[j] = Vs[ll][ee0 + j];
#pragma unroll
            for (int i = 0; i < 4; i++)
#pragma unroll
                for (int j = 0; j < 4; j++)
                    acc[i][j] = fmaf(ka[i], vb[j], acc[i][j]);
        }
        __syncthreads();
    }

    // write attn (scaled 1/N) into Vs storage
#pragma unroll
    for (int i = 0; i < 4; i++)
#pragma unroll
        for (int j = 0; j < 4; j++)
            Atn[(dd0 + i) * 64 + ee0 + j] = acc[i][j] * (1.0f / 1024.0f);
    __syncthreads();

    // ---- phase 2: out = Q @ attn ----
    int eeo = (tid >> 4) << 2;       // output channel group
    int lr0 = (tid & 15) << 2;       // l-row group (consecutive threads -> consecutive nn)
    for (int l0 = 0; l0 < 2048; l0 += 64) {
        int t   = (n_ << 1) + (l0 >> 10);
        int nn0 = l0 & 1023;
        size_t base = ((size_t)(t * BB + b) * CC + h * DH + ldd) * VV + nn0 + llb;
#pragma unroll
        for (int u = 0; u < 16; u += 4) {
            float4 q4 = *(const float4*)(q + base + u);
            Ks[llb + u + 0][ldd] = q4.x;
            Ks[llb + u + 1][ldd] = q4.y;
            Ks[llb + u + 2][ldd] = q4.z;
            Ks[llb + u + 3][ldd] = q4.w;
        }
        __syncthreads();
        float o[4][4];
#pragma unroll
        for (int i = 0; i < 4; i++)
#pragma unroll
            for (int j = 0; j < 4; j++) o[i][j] = 0.f;
#pragma unroll 4
        for (int dd = 0; dd < 64; dd++) {
            float qa[4], ab[4];
#pragma unroll
            for (int i = 0; i < 4; i++) qa[i] = Ks[lr0 + i][dd];
#pragma unroll
            for (int j = 0; j < 4; j++) ab[j] = Atn[dd * 64 + eeo + j];
#pragma unroll
            for (int i = 0; i < 4; i++)
#pragma unroll
                for (int j = 0; j < 4; j++)
                    o[i][j] = fmaf(qa[i], ab[j], o[i][j]);
        }
#pragma unroll
        for (int j = 0; j < 4; j++) {
            size_t yb = ((size_t)(t * BB + b) * CC + h * DH + eeo + j) * VV + nn0 + lr0;
            float4 w4 = make_float4(o[0][j], o[1][j], o[2][j], o[3][j]);
            *(float4*)(y + yb) = w4;
        }
        __syncthreads();
    }
}

// ---------------- v output transpose: (T,B,C,V) -> (T,B,H,N,d) ----------------
__global__ void vout_kernel(const float* __restrict__ vsp, float* __restrict__ out)
{
    __shared__ float tile[32][33];
    int tbh = blockIdx.z;            // 0..255
    int tb = tbh >> 3, h = tbh & 7;
    int n0 = blockIdx.x * 32, dd0 = blockIdx.y * 32;
    int tx = threadIdx.x, ty = threadIdx.y;
    tile[ty][tx] = vsp[((size_t)tb * CC + h * DH + dd0 + ty) * VV + n0 + tx];
    __syncthreads();
    out[((size_t)(tb * NH + h) * VV + n0 + ty) * DH + dd0 + tx] = tile[tx][ty];
}

// ---------------- host launcher ----------------
extern "C" void kernel_launch(void* const* d_in, const int* in_sizes, int n_in,
                              void* d_out, int out_size)
{
    const float* x    = (const float*)d_in[0];
    const float* qw   = (const float*)d_in[1];
    const float* qs   = (const float*)d_in[2];
    const float* qb   = (const float*)d_in[3];
    const float* kw   = (const float*)d_in[4];
    const float* ks_  = (const float*)d_in[5];
    const float* kb   = (const float*)d_in[6];
    const float* vw   = (const float*)d_in[7];
    const float* vs   = (const float*)d_in[8];
    const float* vb   = (const float*)d_in[9];
    const float* pw   = (const float*)d_in[10];
    const float* pwb  = (const float*)d_in[11];
    const float* ps   = (const float*)d_in[12];
    const float* psb  = (const float*)d_in[13];
    const float* f1w  = (const float*)d_in[14];
    const float* f1b  = (const float*)d_in[15];
    const float* f1s  = (const float*)d_in[16];
    const float* f1sb = (const float*)d_in[17];
    const float* f2w  = (const float*)d_in[18];
    const float* f2b  = (const float*)d_in[19];
    const float* f2s  = (const float*)d_in[20];
    const float* f2sb = (const float*)d_in[21];

    float *xs, *zq, *zk, *zv, *yb, *xattn, *m1, *hid;
    cudaGetSymbolAddress((void**)&xs,    g_xs);
    cudaGetSymbolAddress((void**)&zq,    g_zq);
    cudaGetSymbolAddress((void**)&zk,    g_zk);
    cudaGetSymbolAddress((void**)&zv,    g_zv);
    cudaGetSymbolAddress((void**)&yb,    g_y);
    cudaGetSymbolAddress((void**)&xattn, g_xattn);
    cudaGetSymbolAddress((void**)&m1,    g_m1);
    cudaGetSymbolAddress((void**)&hid,   g_hid);

    float* out = (float*)d_out;

    const int lifBlocks  = NPER  / 4 / 256;   // 4096
    const int lifBlocksH = NPERH / 4 / 256;   // 16384

    // 1. shortcut LIF on x
    lif4_kernel<<<lifBlocks, 256>>>(x, xs, 1.0f, NPER);

    // 2. q/k/v conv1x1 + BN affine (batched GEMM)
    dim3 gC(VV / 128, CC / 128, NTB);   // (8,4,32)
    gemm_epi_kernel<<<gC, 256>>>(qw, xs, zq, nullptr, qs,  qb, nullptr, CC, VV, CC);
    gemm_epi_kernel<<<gC, 256>>>(kw, xs, zk, nullptr, ks_, kb, nullptr, CC, VV, CC);
    gemm_epi_kernel<<<gC, 256>>>(vw, xs, zv, nullptr, vs,  vb, nullptr, CC, VV, CC);

    // 3. q/k/v LIF (in place)
    lif4_kernel<<<lifBlocks, 256>>>(zq, zq, 1.0f, NPER);
    lif4_kernel<<<lifBlocks, 256>>>(zk, zk, 1.0f, NPER);
    lif4_kernel<<<lifBlocks, 256>>>(zv, zv, 1.0f, NPER);

    // 4. chunked linear attention -> y
    attn_kernel<<<128, 256>>>(zq, zk, zv, yb);

    // 5. attn LIF (v_th = 0.5, in place)
    lif4_kernel<<<lifBlocks, 256>>>(yb, yb, 0.5f, NPER);

    // 6. projection conv + bias + BN + residual(x) -> x_attn
    gemm_epi_kernel<<<gC, 256>>>(pw, yb, xattn, pwb, ps, psb, x, CC, VV, CC);

    // 7. MLP lif1 (not in place: x_attn needed as residual later)
    lif4_kernel<<<lifBlocks, 256>>>(xattn, m1, 1.0f, NPER);

    // 8. fc1 + bias + BN -> hid
    dim3 gH(VV / 128, HID / 128, NTB);  // (8,16,32)
    gemm_epi_kernel<<<gH, 256>>>(f1w, m1, hid, f1b, f1s, f1sb, nullptr, HID, VV, CC);

    // 9. MLP lif2 (in place)
    lif4_kernel<<<lifBlocksH, 256>>>(hid, hid, 1.0f, NPERH);

    // 10. fc2 + bias + BN + residual(x_attn) -> main output
    gemm_epi_kernel<<<gC, 256>>>(f2w, hid, out, f2b, f2s, f2sb, xattn, CC, VV, HID);

    // 11. second output: v spikes in heads layout (T,B,H,N,d)
    if (out_size >= 2 * MAIN_ELEMS) {
        dim3 gt(VV / 32, DH / 32, NTB * NH);  // (32,2,256)
        vout_kernel<<<gt, dim3(32, 32)>>>(zv, out + MAIN_ELEMS);
    }
}

// round 2
// speedup vs baseline: 4.8065x; 4.8065x over previous
#include <cuda_runtime.h>
#include <cstddef>
#include <cstdint>

// ---------------- problem constants ----------------
#define TT   4
#define BB   8
#define CC   512
#define VV   1024
#define HID  2048
#define NH   8
#define DH   64
#define NTB  (TT*BB)              // 32
#define NPER (BB*CC*VV)           // 4,194,304
#define NPERH (BB*HID*VV)         // 16,777,216
#define MAIN_ELEMS (TT*BB*CC*VV)  // 16,777,216
#define NCOLS (NTB*VV)            // 32768 spike columns

// ---------------- scratch (device globals; no allocation allowed) ----------------
// All activation tensors live in TRANSPOSED layout: [tb][v][c] (c contiguous)
__device__ float g_xt[MAIN_ELEMS];     // x transposed
__device__ float g_xs[MAIN_ELEMS];     // shortcut spikes
__device__ float g_zq[MAIN_ELEMS];
__device__ float g_zk[MAIN_ELEMS];
__device__ float g_zv[MAIN_ELEMS];
__device__ float g_y [MAIN_ELEMS];     // attn out, then spikes in place
__device__ float g_xattn[MAIN_ELEMS];
__device__ float g_m1[MAIN_ELEMS];
__device__ float g_f2[MAIN_ELEMS];
__device__ float g_hid[TT*BB*HID*VV];  // 67,108,864
// transposed weights WT[K][M]
__device__ float g_wq[CC*CC];
__device__ float g_wk[CC*CC];
__device__ float g_wv[CC*CC];
__device__ float g_wp[CC*CC];
__device__ float g_wf1[CC*HID];
__device__ float g_wf2[HID*CC];
// attention partials: [seg(8)][idx(128)][64*64]
__device__ float g_attnp[8*128*4096];

// ---------------- generic 32x32 tiled transpose: out[z][c][r] = in[z][r][c] ----------------
__global__ void tkern(const float* __restrict__ in, float* __restrict__ out,
                      int R, int Cn)
{
    __shared__ float t[32][33];
    size_t bs = (size_t)R * Cn * blockIdx.z;
    int r0 = blockIdx.y * 32, c0 = blockIdx.x * 32;
    int tx = threadIdx.x, ty = threadIdx.y;
#pragma unroll
    for (int j = 0; j < 4; j++)
        t[ty + 8 * j][tx] = in[bs + (size_t)(r0 + ty + 8 * j) * Cn + c0 + tx];
    __syncthreads();
#pragma unroll
    for (int j = 0; j < 4; j++)
        out[bs + (size_t)(c0 + ty + 8 * j) * R + r0 + tx] = t[tx][ty + 8 * j];
}

// ---------------- transpose + add (final output): out[z][c][v] = a[z][v][c] + b[z][v][c] ----
__global__ void taddkern(const float* __restrict__ a, const float* __restrict__ b,
                         float* __restrict__ out)
{
    __shared__ float t[32][33];
    size_t bs = (size_t)VV * CC * blockIdx.z;
    int v0 = blockIdx.y * 32, c0 = blockIdx.x * 32;
    int tx = threadIdx.x, ty = threadIdx.y;
#pragma unroll
    for (int j = 0; j < 4; j++) {
        size_t idx = bs + (size_t)(v0 + ty + 8 * j) * CC + c0 + tx;
        t[ty + 8 * j][tx] = a[idx] + b[idx];
    }
    __syncthreads();
#pragma unroll
    for (int j = 0; j < 4; j++)
        out[bs + (size_t)(c0 + ty + 8 * j) * VV + v0 + tx] = t[tx][ty + 8 * j];
}

// ---------------- LIF: tau=2, hard reset; layout-agnostic (t stride = nper) ----------------
__global__ void lif4_kernel(const float* __restrict__ x, float* __restrict__ s,
                            float vth, int nper)
{
    int i = (blockIdx.x * blockDim.x + threadIdx.x) * 4;
    if (i >= nper) return;
    float4 v = make_float4(0.f, 0.f, 0.f, 0.f);
#pragma unroll
    for (int t = 0; t < TT; t++) {
        float4 xt = *(const float4*)(x + (size_t)t * nper + i);
        float4 h, sp;
        h.x = v.x + (xt.x - v.x) * 0.5f;
        h.y = v.y + (xt.y - v.y) * 0.5f;
        h.z = v.z + (xt.z - v.z) * 0.5f;
        h.w = v.w + (xt.w - v.w) * 0.5f;
        sp.x = (h.x >= vth) ? 1.f : 0.f;
        sp.y = (h.y >= vth) ? 1.f : 0.f;
        sp.z = (h.z >= vth) ? 1.f : 0.f;
        sp.w = (h.w >= vth) ? 1.f : 0.f;
        v.x = (sp.x > 0.f) ? 0.f : h.x;
        v.y = (sp.y > 0.f) ? 0.f : h.y;
        v.z = (sp.z > 0.f) ? 0.f : h.z;
        v.w = (sp.w > 0.f) ? 0.f : h.w;
        *(float4*)(s + (size_t)t * nper + i) = sp;
    }
}

// ---------------- sparse binary GEMM ----------------
// One block per output column (tb,v). XT: [col][K] spikes (contiguous).
// WT: [K][M]. YT: [col][M]. Y[m] = (sum_{k:X=1} WT[k][m] + cb[m])*sc[m] + bb[m] (+ resT[col][m])
template<int K, int M, int MPT>   // MPT = M/256
__global__ __launch_bounds__(256)
void spgemm_kernel(const float* __restrict__ XT, const float* __restrict__ WT,
                   float* __restrict__ YT,
                   const float* __restrict__ cb, const float* __restrict__ sc,
                   const float* __restrict__ bb, const float* __restrict__ resT)
{
    int col = blockIdx.x;
    const float* xc = XT + (size_t)col * K;
    __shared__ uint32_t msk[K / 32];
    int tid = threadIdx.x, wid = tid >> 5, lane = tid & 31;
#pragma unroll
    for (int ch = wid; ch < K / 32; ch += 8) {
        float v = xc[ch * 32 + lane];
        uint32_t m = __ballot_sync(0xffffffffu, v != 0.0f);
        if (lane == 0) msk[ch] = m;
    }
    __syncthreads();

    float acc[MPT];
#pragma unroll
    for (int r = 0; r < MPT; r++) acc[r] = 0.f;

#pragma unroll 1
    for (int w = 0; w < K / 32; w++) {
        uint32_t m = msk[w];
        while (m) {
            int bi = __ffs(m) - 1;
            m &= m - 1;
            const float* wr = WT + (size_t)(w * 32 + bi) * M + tid * 2;
#pragma unroll
            for (int c = 0; c < MPT / 2; c++) {
                float2 wv = *(const float2*)(wr + c * 512);
                acc[2 * c]     += wv.x;
                acc[2 * c + 1] += wv.y;
            }
        }
    }

    size_t ybase = (size_t)col * M;
#pragma unroll
    for (int c = 0; c < MPT / 2; c++) {
        int m = tid * 2 + c * 512;
        float a0 = acc[2 * c];
        float a1 = acc[2 * c + 1];
        if (cb) { a0 += cb[m]; a1 += cb[m + 1]; }
        float2 o;
        o.x = a0 * sc[m]     + bb[m];
        o.y = a1 * sc[m + 1] + bb[m + 1];
        if (resT) {
            float2 r2 = *(const float2*)(resT + ybase + m);
            o.x += r2.x; o.y += r2.y;
        }
        *(float2*)(YT + ybase + m) = o;
    }
}

// ---------------- attention phase 1: partial attn = K^T V over l-segment ----------------
// grid (8 segs, 128 idx). idx = (n_,b,h). l = seg*256 + tile*64 + lr.
__global__ __launch_bounds__(256)
void attn1_kernel(const float* __restrict__ kT, const float* __restrict__ vT,
                  float* __restrict__ attnp)
{
    int idx = blockIdx.y;
    int seg = blockIdx.x;
    int h = idx & 7, b = (idx >> 3) & 7, n_ = idx >> 6;
    int t = (n_ << 1) + (seg >> 2);
    int nnb = (seg & 3) << 8;

    __shared__ float Ks[64][68];
    __shared__ float Vs[64][68];
    int tid = threadIdx.x;
    int lr = tid >> 2, du = (tid & 3) << 4;
    int dd0 = (tid >> 4) << 2, ee0 = (tid & 15) << 2;

    float acc[4][4];
#pragma unroll
    for (int i = 0; i < 4; i++)
#pragma unroll
        for (int j = 0; j < 4; j++) acc[i][j] = 0.f;

    for (int tile = 0; tile < 4; tile++) {
        size_t base = ((size_t)((t * 8 + b) * 1024) + nnb + tile * 64 + lr) * 512 + h * 64 + du;
#pragma unroll
        for (int u = 0; u < 4; u++) {
            *(float4*)&Ks[lr][du + u * 4] = *(const float4*)(kT + base + u * 4);
            *(float4*)&Vs[lr][du + u * 4] = *(const float4*)(vT + base + u * 4);
        }
        __syncthreads();
#pragma unroll 4
        for (int ll = 0; ll < 64; ll++) {
            float ka[4], vb[4];
#pragma unroll
            for (int i = 0; i < 4; i++) ka[i] = Ks[ll][dd0 + i];
#pragma unroll
            for (int j = 0; j < 4; j++) vb[j] = Vs[ll][ee0 + j];
#pragma unroll
            for (int i = 0; i < 4; i++)
#pragma unroll
                for (int j = 0; j < 4; j++)
                    acc[i][j] = fmaf(ka[i], vb[j], acc[i][j]);
        }
        __syncthreads();
    }

    float* dst = attnp + ((size_t)seg * 128 + idx) * 4096;
#pragma unroll
    for (int i = 0; i < 4; i++)
#pragma unroll
        for (int j = 0; j < 4; j++)
            dst[(dd0 + i) * 64 + ee0 + j] = acc[i][j] * (1.0f / 1024.0f);
}

// ---------------- attention phase 2: out = Q @ attn ----------------
// grid (32 l-tiles, 128 idx)
__global__ __launch_bounds__(256)
void attn2_kernel(const float* __restrict__ qT, const float* __restrict__ attnp,
                  float* __restrict__ yT)
{
    int idx = blockIdx.y, ltile = blockIdx.x;
    int h = idx & 7, b = (idx >> 3) & 7, n_ = idx >> 6;
    int t = (n_ << 1) + (ltile >> 4);
    int nn0 = (ltile & 15) << 6;

    __shared__ float Qs[64][68];
    __shared__ float Atn[4096];
    int tid = threadIdx.x;

    for (int i = tid; i < 4096; i += 256) {
        float s = 0.f;
#pragma unroll
        for (int sg = 0; sg < 8; sg++)
            s += attnp[((size_t)sg * 128 + idx) * 4096 + i];
        Atn[i] = s;
    }

    int lr = tid >> 2, du = (tid & 3) << 4;
    size_t rowbase = (size_t)((t * 8 + b) * 1024) + nn0;
    size_t base = (rowbase + lr) * 512 + h * 64 + du;
#pragma unroll
    for (int u = 0; u < 4; u++)
        *(float4*)&Qs[lr][du + u * 4] = *(const float4*)(qT + base + u * 4);
    __syncthreads();

    int lr0 = (tid >> 4) << 2, e0 = (tid & 15) << 2;
    float o[4][4];
#pragma unroll
    for (int i = 0; i < 4; i++)
#pragma unroll
        for (int j = 0; j < 4; j++) o[i][j] = 0.f;
#pragma unroll 4
    for (int dd = 0; dd < 64; dd++) {
        float qa[4], ab[4];
#pragma unroll
        for (int i = 0; i < 4; i++) qa[i] = Qs[lr0 + i][dd];
#pragma unroll
        for (int j = 0; j < 4; j++) ab[j] = Atn[dd * 64 + e0 + j];
#pragma unroll
        for (int i = 0; i < 4; i++)
#pragma unroll
            for (int j = 0; j < 4; j++)
                o[i][j] = fmaf(qa[i], ab[j], o[i][j]);
    }
#pragma unroll
    for (int i = 0; i < 4; i++) {
        size_t ob = (rowbase + lr0 + i) * 512 + h * 64 + e0;
        *(float4*)(yT + ob) = make_float4(o[i][0], o[i][1], o[i][2], o[i][3]);
    }
}

// ---------------- v output: (T,B,H,N,d) gather from zvT [tb][v][c] ----------------
__global__ void voutk(const float* __restrict__ zvT, float* __restrict__ out)
{
    int i = (blockIdx.x * 256 + threadIdx.x) * 4;
    int d  = i & 63;
    int v  = (i >> 6) & 1023;
    int h  = (i >> 16) & 7;
    int tb = i >> 19;
    size_t in = ((size_t)tb * 1024 + v) * 512 + h * 64 + d;
    *(float4*)(out + i) = *(const float4*)(zvT + in);
}

// ---------------- host launcher ----------------
extern "C" void kernel_launch(void* const* d_in, const int* in_sizes, int n_in,
                              void* d_out, int out_size)
{
    const float* x    = (const float*)d_in[0];
    const float* qw   = (const float*)d_in[1];
    const float* qs   = (const float*)d_in[2];
    const float* qb   = (const float*)d_in[3];
    const float* kw   = (const float*)d_in[4];
    const float* ks_  = (const float*)d_in[5];
    const float* kb   = (const float*)d_in[6];
    const float* vw   = (const float*)d_in[7];
    const float* vs   = (const float*)d_in[8];
    const float* vb   = (const float*)d_in[9];
    const float* pw   = (const float*)d_in[10];
    const float* pwb  = (const float*)d_in[11];
    const float* ps   = (const float*)d_in[12];
    const float* psb  = (const float*)d_in[13];
    const float* f1w  = (const float*)d_in[14];
    const float* f1b  = (const float*)d_in[15];
    const float* f1s  = (const float*)d_in[16];
    const float* f1sb = (const float*)d_in[17];
    const float* f2w  = (const float*)d_in[18];
    const float* f2b  = (const float*)d_in[19];
    const float* f2s  = (const float*)d_in[20];
    const float* f2sb = (const float*)d_in[21];

    float *xt, *xs, *zq, *zk, *zv, *yb, *xattn, *m1, *f2o, *hid;
    float *wq, *wk, *wv, *wp, *wf1, *wf2, *attnp;
    cudaGetSymbolAddress((void**)&xt,    g_xt);
    cudaGetSymbolAddress((void**)&xs,    g_xs);
    cudaGetSymbolAddress((void**)&zq,    g_zq);
    cudaGetSymbolAddress((void**)&zk,    g_zk);
    cudaGetSymbolAddress((void**)&zv,    g_zv);
    cudaGetSymbolAddress((void**)&yb,    g_y);
    cudaGetSymbolAddress((void**)&xattn, g_xattn);
    cudaGetSymbolAddress((void**)&m1,    g_m1);
    cudaGetSymbolAddress((void**)&f2o,   g_f2);
    cudaGetSymbolAddress((void**)&hid,   g_hid);
    cudaGetSymbolAddress((void**)&wq,    g_wq);
    cudaGetSymbolAddress((void**)&wk,    g_wk);
    cudaGetSymbolAddress((void**)&wv,    g_wv);
    cudaGetSymbolAddress((void**)&wp,    g_wp);
    cudaGetSymbolAddress((void**)&wf1,   g_wf1);
    cudaGetSymbolAddress((void**)&wf2,   g_wf2);
    cudaGetSymbolAddress((void**)&attnp, g_attnp);

    float* out = (float*)d_out;

    dim3 tb32(32, 8);
    // weight transposes: WT[k][m] = W[m][k]
    tkern<<<dim3(CC / 32, CC / 32, 1), tb32>>>(qw,  wq,  CC,  CC);
    tkern<<<dim3(CC / 32, CC / 32, 1), tb32>>>(kw,  wk,  CC,  CC);
    tkern<<<dim3(CC / 32, CC / 32, 1), tb32>>>(vw,  wv,  CC,  CC);
    tkern<<<dim3(CC / 32, CC / 32, 1), tb32>>>(pw,  wp,  CC,  CC);
    tkern<<<dim3(CC / 32, HID / 32, 1), tb32>>>(f1w, wf1, HID, CC);   // [512][2048]
    tkern<<<dim3(HID / 32, CC / 32, 1), tb32>>>(f2w, wf2, CC,  HID);  // [2048][512]

    // x -> transposed layout [tb][v][c]
    tkern<<<dim3(VV / 32, CC / 32, NTB), tb32>>>(x, xt, CC, VV);

    const int lifBlocks  = NPER  / 4 / 256;
    const int lifBlocksH = NPERH / 4 / 256;

    // 1. shortcut LIF
    lif4_kernel<<<lifBlocks, 256>>>(xt, xs, 1.0f, NPER);

    // 2. q/k/v sparse conv1x1 + BN
    spgemm_kernel<CC, CC, 2><<<NCOLS, 256>>>(xs, wq, zq, nullptr, qs,  qb, nullptr);
    spgemm_kernel<CC, CC, 2><<<NCOLS, 256>>>(xs, wk, zk, nullptr, ks_, kb, nullptr);
    spgemm_kernel<CC, CC, 2><<<NCOLS, 256>>>(xs, wv, zv, nullptr, vs,  vb, nullptr);

    // 3. q/k/v LIF (in place)
    lif4_kernel<<<lifBlocks, 256>>>(zq, zq, 1.0f, NPER);
    lif4_kernel<<<lifBlocks, 256>>>(zk, zk, 1.0f, NPER);
    lif4_kernel<<<lifBlocks, 256>>>(zv, zv, 1.0f, NPER);

    // 4. chunked linear attention
    attn1_kernel<<<dim3(8, 128), 256>>>(zk, zv, attnp);
    attn2_kernel<<<dim3(32, 128), 256>>>(zq, attnp, yb);

    // 5. attn LIF (v_th = 0.5)
    lif4_kernel<<<lifBlocks, 256>>>(yb, yb, 0.5f, NPER);

    // 6. projection + bias + BN + residual(x) -> xattn
    spgemm_kernel<CC, CC, 2><<<NCOLS, 256>>>(yb, wp, xattn, pwb, ps, psb, xt);

    // 7. MLP lif1
    lif4_kernel<<<lifBlocks, 256>>>(xattn, m1, 1.0f, NPER);

    // 8. fc1 + bias + BN
    spgemm_kernel<CC, HID, 8><<<NCOLS, 256>>>(m1, wf1, hid, f1b, f1s, f1sb, nullptr);

    // 9. MLP lif2 (in place)
    lif4_kernel<<<lifBlocksH, 256>>>(hid, hid, 1.0f, NPERH);

    // 10. fc2 + bias + BN -> f2o (transposed)
    spgemm_kernel<HID, CC, 2><<<NCOLS, 256>>>(hid, wf2, f2o, f2b, f2s, f2sb, nullptr);

    // 11. main output: transpose-add back to (T,B,C,V)
    taddkern<<<dim3(CC / 32, VV / 32, NTB), tb32>>>(f2o, xattn, out);

    // 12. second output: v spikes in heads layout
    if (out_size >= 2 * MAIN_ELEMS) {
        voutk<<<MAIN_ELEMS / 1024, 256>>>(zv, out + MAIN_ELEMS);
    }
}

// round 3
// speedup vs baseline: 5.8627x; 1.2198x over previous
#include <cuda_runtime.h>
#include <cstddef>
#include <cstdint>

// ---------------- problem constants ----------------
#define TT   4
#define BB   8
#define CC   512
#define VV   1024
#define HID  2048
#define NH   8
#define DH   64
#define NTB  (TT*BB)              // 32
#define NPER (BB*CC*VV)           // 4,194,304
#define MAIN_ELEMS (TT*BB*CC*VV)  // 16,777,216
#define NBV  (BB*VV)              // 8192 (b,v) columns

// ---------------- scratch ----------------
__device__ float g_xt[MAIN_ELEMS];     // x transposed [tb][v][c]
__device__ float g_zq[MAIN_ELEMS];
__device__ float g_zk[MAIN_ELEMS];
__device__ float g_zv[MAIN_ELEMS];
__device__ float g_y [MAIN_ELEMS];     // attention output (pre-LIF)
__device__ float g_f2[MAIN_ELEMS];     // final sum, transposed
__device__ float g_wqkv[CC*3*CC];      // interleaved [k][q512|k512|v512]
__device__ float g_wp [CC*CC];
__device__ float g_wf1[CC*HID];
__device__ float g_wf2[HID*CC];
__device__ float g_attnp[8*128*4096];

// ---------------- 32x32 tiled transpose: out[z][c][r] = in[z][r][c] ----------------
__global__ void tkern(const float* __restrict__ in, float* __restrict__ out,
                      int R, int Cn)
{
    __shared__ float t[32][33];
    size_t bs = (size_t)R * Cn * blockIdx.z;
    int r0 = blockIdx.y * 32, c0 = blockIdx.x * 32;
    int tx = threadIdx.x, ty = threadIdx.y;
#pragma unroll
    for (int j = 0; j < 4; j++)
        t[ty + 8 * j][tx] = in[bs + (size_t)(r0 + ty + 8 * j) * Cn + c0 + tx];
    __syncthreads();
#pragma unroll
    for (int j = 0; j < 4; j++)
        out[bs + (size_t)(c0 + ty + 8 * j) * R + r0 + tx] = t[tx][ty + 8 * j];
}

// ---------------- interleaved qkv weight transpose: wqkv[k][z*512+m] = W_z[m][k] ----
__global__ void qkvw_kern(const float* __restrict__ qw, const float* __restrict__ kw,
                          const float* __restrict__ vw, float* __restrict__ wqkv)
{
    __shared__ float t[32][33];
    const float* src = (blockIdx.z == 0) ? qw : (blockIdx.z == 1) ? kw : vw;
    int m0 = blockIdx.y * 32, k0 = blockIdx.x * 32;
    int tx = threadIdx.x, ty = threadIdx.y;
#pragma unroll
    for (int j = 0; j < 4; j++)
        t[ty + 8 * j][tx] = src[(size_t)(m0 + ty + 8 * j) * CC + k0 + tx];
    __syncthreads();
#pragma unroll
    for (int j = 0; j < 4; j++)
        wqkv[(size_t)(k0 + ty + 8 * j) * 1536 + blockIdx.z * 512 + m0 + tx] = t[tx][ty + 8 * j];
}

// ---------------- Kernel A: fused shortcut-LIF + qkv conv/BN + qkv-LIF ----------------
// one block per (b,v); thread tid owns mask channels {tid, tid+256} and gather channels {2tid, 2tid+1}
__global__ __launch_bounds__(256)
void qkv_kernel(const float* __restrict__ xt, const float* __restrict__ wqkv,
                float* __restrict__ zq, float* __restrict__ zk, float* __restrict__ zv,
                const float* __restrict__ qs, const float* __restrict__ qb,
                const float* __restrict__ ks_, const float* __restrict__ kb,
                const float* __restrict__ vs, const float* __restrict__ vb)
{
    int col = blockIdx.x;
    int b = col >> 10, v = col & 1023;
    int tid = threadIdx.x, wid = tid >> 5, lane = tid & 31;
    __shared__ uint32_t mx[4][16];

    // phase 1: LIF(1.0) on x -> spike masks per t
    {
        float v0 = 0.f, v1 = 0.f;
#pragma unroll
        for (int t = 0; t < 4; t++) {
            size_t base = ((size_t)((t * 8 + b) * 1024 + v)) * 512;
            float x0 = xt[base + tid], x1 = xt[base + tid + 256];
            float h0 = v0 + (x0 - v0) * 0.5f, h1 = v1 + (x1 - v1) * 0.5f;
            bool s0 = (h0 >= 1.f), s1 = (h1 >= 1.f);
            v0 = s0 ? 0.f : h0; v1 = s1 ? 0.f : h1;
            uint32_t m0 = __ballot_sync(0xffffffffu, s0);
            uint32_t m1 = __ballot_sync(0xffffffffu, s1);
            if (lane == 0) { mx[t][wid] = m0; mx[t][8 + wid] = m1; }
        }
    }
    __syncthreads();

    int c0 = tid * 2;
    float2 qs2 = *(const float2*)(qs + c0), qb2 = *(const float2*)(qb + c0);
    float2 ks2 = *(const float2*)(ks_ + c0), kb2 = *(const float2*)(kb + c0);
    float2 vs2 = *(const float2*)(vs + c0), vb2 = *(const float2*)(vb + c0);

    float vq0 = 0.f, vq1 = 0.f, vk0 = 0.f, vk1 = 0.f, vv0 = 0.f, vv1 = 0.f;
#pragma unroll 1
    for (int t = 0; t < 4; t++) {
        float aq0 = 0.f, aq1 = 0.f, ak0 = 0.f, ak1 = 0.f, av0 = 0.f, av1 = 0.f;
#pragma unroll 1
        for (int w = 0; w < 16; w++) {
            uint32_t m = mx[t][w];
            while (m) {
                int bi = __ffs(m) - 1;
                m &= m - 1;
                const float* wr = wqkv + (size_t)(w * 32 + bi) * 1536 + c0;
                float2 wq2 = *(const float2*)(wr);
                float2 wk2 = *(const float2*)(wr + 512);
                float2 wv2 = *(const float2*)(wr + 1024);
                aq0 += wq2.x; aq1 += wq2.y;
                ak0 += wk2.x; ak1 += wk2.y;
                av0 += wv2.x; av1 += wv2.y;
            }
        }
        // BN + LIF(1.0) -> spikes
        float p, h;
        size_t obase = ((size_t)((t * 8 + b) * 1024 + v)) * 512 + c0;
        float2 o;
        p = aq0 * qs2.x + qb2.x; h = vq0 + (p - vq0) * 0.5f; o.x = (h >= 1.f) ? 1.f : 0.f; vq0 = (h >= 1.f) ? 0.f : h;
        p = aq1 * qs2.y + qb2.y; h = vq1 + (p - vq1) * 0.5f; o.y = (h >= 1.f) ? 1.f : 0.f; vq1 = (h >= 1.f) ? 0.f : h;
        *(float2*)(zq + obase) = o;
        p = ak0 * ks2.x + kb2.x; h = vk0 + (p - vk0) * 0.5f; o.x = (h >= 1.f) ? 1.f : 0.f; vk0 = (h >= 1.f) ? 0.f : h;
        p = ak1 * ks2.y + kb2.y; h = vk1 + (p - vk1) * 0.5f; o.y = (h >= 1.f) ? 1.f : 0.f; vk1 = (h >= 1.f) ? 0.f : h;
        *(float2*)(zk + obase) = o;
        p = av0 * vs2.x + vb2.x; h = vv0 + (p - vv0) * 0.5f; o.x = (h >= 1.f) ? 1.f : 0.f; vv0 = (h >= 1.f) ? 0.f : h;
        p = av1 * vs2.y + vb2.y; h = vv1 + (p - vv1) * 0.5f; o.y = (h >= 1.f) ? 1.f : 0.f; vv1 = (h >= 1.f) ? 0.f : h;
        *(float2*)(zv + obase) = o;
    }
}

// ---------------- Kernel B: fused attn-LIF + proj/BN + residual + MLP ----------------
// one block per (b,v); mask channels {tid, tid+256(+256r)}
__global__ __launch_bounds__(256)
void pmlp_kernel(const float* __restrict__ yb, const float* __restrict__ xt,
                 const float* __restrict__ wp, const float* __restrict__ wf1,
                 const float* __restrict__ wf2,
                 const float* __restrict__ pwb, const float* __restrict__ ps, const float* __restrict__ psb,
                 const float* __restrict__ f1b, const float* __restrict__ f1s, const float* __restrict__ f1sb,
                 const float* __restrict__ f2b, const float* __restrict__ f2s, const float* __restrict__ f2sb,
                 float* __restrict__ f2o)
{
    int col = blockIdx.x;
    int b = col >> 10, v = col & 1023;
    int tid = threadIdx.x, wid = tid >> 5, lane = tid & 31;
    __shared__ uint32_t mpr[4][16];
    __shared__ uint32_t mm1[16];
    __shared__ uint32_t mh[64];

    // phase 1: LIF(0.5) on attention output -> proj-input masks
    {
        float v0 = 0.f, v1 = 0.f;
#pragma unroll
        for (int t = 0; t < 4; t++) {
            size_t base = ((size_t)((t * 8 + b) * 1024 + v)) * 512;
            float x0 = yb[base + tid], x1 = yb[base + tid + 256];
            float h0 = v0 + (x0 - v0) * 0.5f, h1 = v1 + (x1 - v1) * 0.5f;
            bool s0 = (h0 >= 0.5f), s1 = (h1 >= 0.5f);
            v0 = s0 ? 0.f : h0; v1 = s1 ? 0.f : h1;
            uint32_t m0 = __ballot_sync(0xffffffffu, s0);
            uint32_t m1 = __ballot_sync(0xffffffffu, s1);
            if (lane == 0) { mpr[t][wid] = m0; mpr[t][8 + wid] = m1; }
        }
    }
    __syncthreads();

    float pwb0 = pwb[tid], pwb1 = pwb[tid + 256];
    float ps0  = ps[tid],  ps1  = ps[tid + 256];
    float psb0 = psb[tid], psb1 = psb[tid + 256];
    float f2b0 = f2b[tid], f2b1 = f2b[tid + 256];
    float f2s0 = f2s[tid], f2s1 = f2s[tid + 256];
    float f2q0 = f2sb[tid], f2q1 = f2sb[tid + 256];

    float vxa0 = 0.f, vxa1 = 0.f;
    float vh[8];
#pragma unroll
    for (int r = 0; r < 8; r++) vh[r] = 0.f;

#pragma unroll 1
    for (int t = 0; t < 4; t++) {
        // --- proj gather ---
        float a0 = 0.f, a1 = 0.f;
#pragma unroll 1
        for (int w = 0; w < 16; w++) {
            uint32_t m = mpr[t][w];
            while (m) {
                int bi = __ffs(m) - 1;
                m &= m - 1;
                const float* wr = wp + (size_t)(w * 32 + bi) * 512;
                a0 += wr[tid]; a1 += wr[tid + 256];
            }
        }
        size_t base = ((size_t)((t * 8 + b) * 1024 + v)) * 512;
        float xa0 = (a0 + pwb0) * ps0 + psb0 + xt[base + tid];
        float xa1 = (a1 + pwb1) * ps1 + psb1 + xt[base + tid + 256];
        // LIF(1.0) -> m1 masks
        {
            float h0 = vxa0 + (xa0 - vxa0) * 0.5f, h1 = vxa1 + (xa1 - vxa1) * 0.5f;
            bool s0 = (h0 >= 1.f), s1 = (h1 >= 1.f);
            vxa0 = s0 ? 0.f : h0; vxa1 = s1 ? 0.f : h1;
            uint32_t m0 = __ballot_sync(0xffffffffu, s0);
            uint32_t m1 = __ballot_sync(0xffffffffu, s1);
            if (lane == 0) { mm1[wid] = m0; mm1[8 + wid] = m1; }
        }
        __syncthreads();   // mm1 visible (prior readers finished at loop-end sync)

        // --- fc1 gather (2048-wide) ---
        float ha[8];
#pragma unroll
        for (int r = 0; r < 8; r++) ha[r] = 0.f;
#pragma unroll 1
        for (int w = 0; w < 16; w++) {
            uint32_t m = mm1[w];
            while (m) {
                int bi = __ffs(m) - 1;
                m &= m - 1;
                const float* wr = wf1 + (size_t)(w * 32 + bi) * 2048 + tid;
#pragma unroll
                for (int r = 0; r < 8; r++) ha[r] += wr[r * 256];
            }
        }
        // BN + LIF(1.0) -> hid masks
#pragma unroll
        for (int r = 0; r < 8; r++) {
            int c = tid + 256 * r;
            float hv = (ha[r] + f1b[c]) * f1s[c] + f1sb[c];
            float h = vh[r] + (hv - vh[r]) * 0.5f;
            bool s = (h >= 1.f);
            vh[r] = s ? 0.f : h;
            uint32_t m = __ballot_sync(0xffffffffu, s);
            if (lane == 0) mh[8 * r + wid] = m;
        }
        __syncthreads();   // mh visible

        // --- fc2 gather ---
        float f0 = 0.f, f1 = 0.f;
#pragma unroll 1
        for (int w = 0; w < 64; w++) {
            uint32_t m = mh[w];
            while (m) {
                int bi = __ffs(m) - 1;
                m &= m - 1;
                const float* wr = wf2 + (size_t)(w * 32 + bi) * 512;
                f0 += wr[tid]; f1 += wr[tid + 256];
            }
        }
        f2o[base + tid]       = (f0 + f2b0) * f2s0 + f2q0 + xa0;
        f2o[base + tid + 256] = (f1 + f2b1) * f2s1 + f2q1 + xa1;
        __syncthreads();   // readers of mm1/mh done before next-iter rebuild
    }
}

// ---------------- attention phase 1: partial attn = K^T V ----------------
__global__ __launch_bounds__(256)
void attn1_kernel(const float* __restrict__ kT, const float* __restrict__ vT,
                  float* __restrict__ attnp)
{
    int idx = blockIdx.y;
    int seg = blockIdx.x;
    int h = idx & 7, b = (idx >> 3) & 7, n_ = idx >> 6;
    int t = (n_ << 1) + (seg >> 2);
    int nnb = (seg & 3) << 8;

    __shared__ float Ks[64][68];
    __shared__ float Vs[64][68];
    int tid = threadIdx.x;
    int lr = tid >> 2, du = (tid & 3) << 4;
    int dd0 = (tid >> 4) << 2, ee0 = (tid & 15) << 2;

    float acc[4][4];
#pragma unroll
    for (int i = 0; i < 4; i++)
#pragma unroll
        for (int j = 0; j < 4; j++) acc[i][j] = 0.f;

    for (int tile = 0; tile < 4; tile++) {
        size_t base = ((size_t)((t * 8 + b) * 1024) + nnb + tile * 64 + lr) * 512 + h * 64 + du;
#pragma unroll
        for (int u = 0; u < 4; u++) {
            *(float4*)&Ks[lr][du + u * 4] = *(const float4*)(kT + base + u * 4);
            *(float4*)&Vs[lr][du + u * 4] = *(const float4*)(vT + base + u * 4);
        }
        __syncthreads();
#pragma unroll 4
        for (int ll = 0; ll < 64; ll++) {
            float ka[4], vb[4];
#pragma unroll
            for (int i = 0; i < 4; i++) ka[i] = Ks[ll][dd0 + i];
#pragma unroll
            for (int j = 0; j < 4; j++) vb[j] = Vs[ll][ee0 + j];
#pragma unroll
            for (int i = 0; i < 4; i++)
#pragma unroll
                for (int j = 0; j < 4; j++)
                    acc[i][j] = fmaf(ka[i], vb[j], acc[i][j]);
        }
        __syncthreads();
    }

    float* dst = attnp + ((size_t)seg * 128 + idx) * 4096;
#pragma unroll
    for (int i = 0; i < 4; i++)
#pragma unroll
        for (int j = 0; j < 4; j++)
            dst[(dd0 + i) * 64 + ee0 + j] = acc[i][j] * (1.0f / 1024.0f);
}

// ---------------- attention phase 2: out = Q @ attn ----------------
__global__ __launch_bounds__(256)
void attn2_kernel(const float* __restrict__ qT, const float* __restrict__ attnp,
                  float* __restrict__ yT)
{
    int idx = blockIdx.y, ltile = blockIdx.x;
    int h = idx & 7, b = (idx >> 3) & 7, n_ = idx >> 6;
    int t = (n_ << 1) + (ltile >> 4);
    int nn0 = (ltile & 15) << 6;

    __shared__ float Qs[64][68];
    __shared__ float Atn[4096];
    int tid = threadIdx.x;

    for (int i = tid; i < 4096; i += 256) {
        float s = 0.f;
#pragma unroll
        for (int sg = 0; sg < 8; sg++)
            s += attnp[((size_t)sg * 128 + idx) * 4096 + i];
        Atn[i] = s;
    }

    int lr = tid >> 2, du = (tid & 3) << 4;
    size_t rowbase = (size_t)((t * 8 + b) * 1024) + nn0;
    size_t base = (rowbase + lr) * 512 + h * 64 + du;
#pragma unroll
    for (int u = 0; u < 4; u++)
        *(float4*)&Qs[lr][du + u * 4] = *(const float4*)(qT + base + u * 4);
    __syncthreads();

    int lr0 = (tid >> 4) << 2, e0 = (tid & 15) << 2;
    float o[4][4];
#pragma unroll
    for (int i = 0; i < 4; i++)
#pragma unroll
        for (int j = 0; j < 4; j++) o[i][j] = 0.f;
#pragma unroll 4
    for (int dd = 0; dd < 64; dd++) {
        float qa[4], ab[4];
#pragma unroll
        for (int i = 0; i < 4; i++) qa[i] = Qs[lr0 + i][dd];
#pragma unroll
        for (int j = 0; j < 4; j++) ab[j] = Atn[dd * 64 + e0 + j];
#pragma unroll
        for (int i = 0; i < 4; i++)
#pragma unroll
            for (int j = 0; j < 4; j++)
                o[i][j] = fmaf(qa[i], ab[j], o[i][j]);
    }
#pragma unroll
    for (int i = 0; i < 4; i++) {
        size_t ob = (rowbase + lr0 + i) * 512 + h * 64 + e0;
        *(float4*)(yT + ob) = make_float4(o[i][0], o[i][1], o[i][2], o[i][3]);
    }
}

// ---------------- v output: (T,B,H,N,d) gather from zvT [tb][v][c] ----------------
__global__ void voutk(const float* __restrict__ zvT, float* __restrict__ out)
{
    int i = (blockIdx.x * 256 + threadIdx.x) * 4;
    int d  = i & 63;
    int v  = (i >> 6) & 1023;
    int h  = (i >> 16) & 7;
    int tb = i >> 19;
    size_t in = ((size_t)tb * 1024 + v) * 512 + h * 64 + d;
    *(float4*)(out + i) = *(const float4*)(zvT + in);
}

// ---------------- host launcher ----------------
extern "C" void kernel_launch(void* const* d_in, const int* in_sizes, int n_in,
                              void* d_out, int out_size)
{
    const float* x    = (const float*)d_in[0];
    const float* qw   = (const float*)d_in[1];
    const float* qs   = (const float*)d_in[2];
    const float* qb   = (const float*)d_in[3];
    const float* kw   = (const float*)d_in[4];
    const float* ks_  = (const float*)d_in[5];
    const float* kb   = (const float*)d_in[6];
    const float* vw   = (const float*)d_in[7];
    const float* vs   = (const float*)d_in[8];
    const float* vb   = (const float*)d_in[9];
    const float* pw   = (const float*)d_in[10];
    const float* pwb  = (const float*)d_in[11];
    const float* ps   = (const float*)d_in[12];
    const float* psb  = (const float*)d_in[13];
    const float* f1w  = (const float*)d_in[14];
    const float* f1b  = (const float*)d_in[15];
    const float* f1s  = (const float*)d_in[16];
    const float* f1sb = (const float*)d_in[17];
    const float* f2w  = (const float*)d_in[18];
    const float* f2b  = (const float*)d_in[19];
    const float* f2s  = (const float*)d_in[20];
    const float* f2sb = (const float*)d_in[21];

    float *xt, *zq, *zk, *zv, *yb, *f2o;
    float *wqkv, *wp, *wf1, *wf2, *attnp;
    cudaGetSymbolAddress((void**)&xt,    g_xt);
    cudaGetSymbolAddress((void**)&zq,    g_zq);
    cudaGetSymbolAddress((void**)&zk,    g_zk);
    cudaGetSymbolAddress((void**)&zv,    g_zv);
    cudaGetSymbolAddress((void**)&yb,    g_y);
    cudaGetSymbolAddress((void**)&f2o,   g_f2);
    cudaGetSymbolAddress((void**)&wqkv,  g_wqkv);
    cudaGetSymbolAddress((void**)&wp,    g_wp);
    cudaGetSymbolAddress((void**)&wf1,   g_wf1);
    cudaGetSymbolAddress((void**)&wf2,   g_wf2);
    cudaGetSymbolAddress((void**)&attnp, g_attnp);

    float* out = (float*)d_out;

    dim3 tb32(32, 8);
    // weight prep
    qkvw_kern<<<dim3(CC / 32, CC / 32, 3), tb32>>>(qw, kw, vw, wqkv);
    tkern<<<dim3(CC / 32, CC / 32, 1), tb32>>>(pw,  wp,  CC,  CC);
    tkern<<<dim3(CC / 32, HID / 32, 1), tb32>>>(f1w, wf1, HID, CC);
    tkern<<<dim3(HID / 32, CC / 32, 1), tb32>>>(f2w, wf2, CC,  HID);

    // x -> transposed layout [tb][v][c]
    tkern<<<dim3(VV / 32, CC / 32, NTB), tb32>>>(x, xt, CC, VV);

    // fused shortcut-LIF + qkv + qkv-LIF
    qkv_kernel<<<NBV, 256>>>(xt, wqkv, zq, zk, zv, qs, qb, ks_, kb, vs, vb);

    // chunked linear attention
    attn1_kernel<<<dim3(8, 128), 256>>>(zk, zv, attnp);
    attn2_kernel<<<dim3(32, 128), 256>>>(zq, attnp, yb);

    // fused attn-LIF + proj + residual + MLP
    pmlp_kernel<<<NBV, 256>>>(yb, xt, wp, wf1, wf2,
                              pwb, ps, psb, f1b, f1s, f1sb, f2b, f2s, f2sb, f2o);

    // main output: transpose back to (T,B,C,V)
    tkern<<<dim3(CC / 32, VV / 32, NTB), tb32>>>(f2o, out, VV, CC);

    // second output: v spikes in heads layout
    if (out_size >= 2 * MAIN_ELEMS) {
        voutk<<<MAIN_ELEMS / 1024, 256>>>(zv, out + MAIN_ELEMS);
    }
}

// round 4
// speedup vs baseline: 6.9902x; 1.1923x over previous
#include <cuda_runtime.h>
#include <cstddef>
#include <cstdint>

// ---------------- problem constants ----------------
#define TT   4
#define BB   8
#define CC   512
#define VV   1024
#define HID  2048
#define NTB  (TT*BB)              // 32
#define MAIN_ELEMS (TT*BB*CC*VV)  // 16,777,216
#define NBV  (BB*VV)              // 8192 (b,v) columns

// ---------------- scratch ----------------
__device__ float g_xt[MAIN_ELEMS];      // x transposed [tb][v][c]
__device__ float g_y [MAIN_ELEMS];      // attention output (pre-LIF) [tb][v][c]
__device__ float g_f2[MAIN_ELEMS];      // final sum, transposed [tb][v][c]
__device__ float g_wqkv[CC*3*CC];       // [k][q512|k512|v512]
__device__ float g_wp [CC*CC];
__device__ float g_wf1[CC*HID];
__device__ float g_wf2[HID*CC];
__device__ uint32_t g_mq[NTB*VV*16];    // spike bitmasks: [tb*1024+v][16 words]
__device__ uint32_t g_mk[NTB*VV*16];
__device__ uint32_t g_mv[NTB*VV*16];
__device__ float g_attn[128*4096];      // per (n_,b,h): 64x64 attn matrix

// ---------------- 32x32 tiled transpose: out[z][c][r] = in[z][r][c] ----------------
__global__ void tkern(const float* __restrict__ in, float* __restrict__ out,
                      int R, int Cn)
{
    __shared__ float t[32][33];
    size_t bs = (size_t)R * Cn * blockIdx.z;
    int r0 = blockIdx.y * 32, c0 = blockIdx.x * 32;
    int tx = threadIdx.x, ty = threadIdx.y;
#pragma unroll
    for (int j = 0; j < 4; j++)
        t[ty + 8 * j][tx] = in[bs + (size_t)(r0 + ty + 8 * j) * Cn + c0 + tx];
    __syncthreads();
#pragma unroll
    for (int j = 0; j < 4; j++)
        out[bs + (size_t)(c0 + ty + 8 * j) * R + r0 + tx] = t[tx][ty + 8 * j];
}

// ---------------- interleaved qkv weight transpose ----------------
__global__ void qkvw_kern(const float* __restrict__ qw, const float* __restrict__ kw,
                          const float* __restrict__ vw, float* __restrict__ wqkv)
{
    __shared__ float t[32][33];
    const float* src = (blockIdx.z == 0) ? qw : (blockIdx.z == 1) ? kw : vw;
    int m0 = blockIdx.y * 32, k0 = blockIdx.x * 32;
    int tx = threadIdx.x, ty = threadIdx.y;
#pragma unroll
    for (int j = 0; j < 4; j++)
        t[ty + 8 * j][tx] = src[(size_t)(m0 + ty + 8 * j) * CC + k0 + tx];
    __syncthreads();
#pragma unroll
    for (int j = 0; j < 4; j++)
        wqkv[(size_t)(k0 + ty + 8 * j) * 1536 + blockIdx.z * 512 + m0 + tx] = t[tx][ty + 8 * j];
}

// ---------------- Kernel A: fused shortcut-LIF + qkv conv/BN + qkv-LIF -> bitmasks ----
__global__ __launch_bounds__(256)
void qkv_kernel(const float* __restrict__ xt, const float* __restrict__ wqkv,
                uint32_t* __restrict__ mq, uint32_t* __restrict__ mkb,
                uint32_t* __restrict__ mv,
                float* __restrict__ vout, int write_v,
                const float* __restrict__ qs, const float* __restrict__ qb,
                const float* __restrict__ ks_, const float* __restrict__ kb,
                const float* __restrict__ vs, const float* __restrict__ vb)
{
    int col = blockIdx.x;
    int b = col >> 10, v = col & 1023;
    int tid = threadIdx.x, wid = tid >> 5, lane = tid & 31;
    __shared__ uint32_t mx[4][16];
    __shared__ uint16_t lst[4][512];
    __shared__ int base[4][17];

    // phase 1: LIF(1.0) on x -> masks
    {
        float v0 = 0.f, v1 = 0.f;
#pragma unroll
        for (int t = 0; t < 4; t++) {
            size_t ib = ((size_t)((t * 8 + b) * 1024 + v)) * 512;
            float x0 = xt[ib + tid], x1 = xt[ib + tid + 256];
            float h0 = v0 + (x0 - v0) * 0.5f, h1 = v1 + (x1 - v1) * 0.5f;
            bool s0 = (h0 >= 1.f), s1 = (h1 >= 1.f);
            v0 = s0 ? 0.f : h0; v1 = s1 ? 0.f : h1;
            uint32_t b0 = __ballot_sync(0xffffffffu, s0);
            uint32_t b1 = __ballot_sync(0xffffffffu, s1);
            if (lane == 0) { mx[t][wid] = b0; mx[t][8 + wid] = b1; }
        }
    }
    __syncthreads();
    // build index lists (deterministic order)
    if (tid < 4) {
        int s = 0;
#pragma unroll
        for (int w = 0; w < 16; w++) { base[tid][w] = s; s += __popc(mx[tid][w]); }
        base[tid][16] = s;
    }
    __syncthreads();
    if (tid < 64) {
        int t = tid >> 4, w = tid & 15;
        uint32_t m = mx[t][w];
        int off = base[t][w];
        while (m) { int bi = __ffs(m) - 1; m &= m - 1; lst[t][off++] = (uint16_t)(w * 32 + bi); }
    }
    __syncthreads();

    float sq0 = qs[tid], sq1 = qs[tid + 256], bq0 = qb[tid], bq1 = qb[tid + 256];
    float sk0 = ks_[tid], sk1 = ks_[tid + 256], bk0 = kb[tid], bk1 = kb[tid + 256];
    float sv0 = vs[tid], sv1 = vs[tid + 256], bv0 = vb[tid], bv1 = vb[tid + 256];

    float vq0 = 0.f, vq1 = 0.f, vk0 = 0.f, vk1 = 0.f, vv0 = 0.f, vv1 = 0.f;
#pragma unroll 1
    for (int t = 0; t < 4; t++) {
        float aq0 = 0.f, aq1 = 0.f, ak0 = 0.f, ak1 = 0.f, av0 = 0.f, av1 = 0.f;
        int n = base[t][16];
        int i = 0;
        for (; i + 2 <= n; i += 2) {
            const float* w0 = wqkv + (size_t)lst[t][i] * 1536;
            const float* w1 = wqkv + (size_t)lst[t][i + 1] * 1536;
            float a0 = w0[tid], a1 = w0[tid + 256], a2 = w0[tid + 512],
                  a3 = w0[tid + 768], a4 = w0[tid + 1024], a5 = w0[tid + 1280];
            float c0 = w1[tid], c1 = w1[tid + 256], c2 = w1[tid + 512],
                  c3 = w1[tid + 768], c4 = w1[tid + 1024], c5 = w1[tid + 1280];
            aq0 += a0; aq1 += a1; ak0 += a2; ak1 += a3; av0 += a4; av1 += a5;
            aq0 += c0; aq1 += c1; ak0 += c2; ak1 += c3; av0 += c4; av1 += c5;
        }
        if (i < n) {
            const float* w0 = wqkv + (size_t)lst[t][i] * 1536;
            aq0 += w0[tid]; aq1 += w0[tid + 256]; ak0 += w0[tid + 512];
            ak1 += w0[tid + 768]; av0 += w0[tid + 1024]; av1 += w0[tid + 1280];
        }

        size_t col16 = ((size_t)((t * 8 + b) * 1024 + v)) * 16;
        float p, h; bool s; uint32_t bl;
        // q
        p = aq0 * sq0 + bq0; h = vq0 + (p - vq0) * 0.5f; s = (h >= 1.f); vq0 = s ? 0.f : h;
        bl = __ballot_sync(0xffffffffu, s); if (lane == 0) mq[col16 + wid] = bl;
        p = aq1 * sq1 + bq1; h = vq1 + (p - vq1) * 0.5f; s = (h >= 1.f); vq1 = s ? 0.f : h;
        bl = __ballot_sync(0xffffffffu, s); if (lane == 0) mq[col16 + 8 + wid] = bl;
        // k
        p = ak0 * sk0 + bk0; h = vk0 + (p - vk0) * 0.5f; s = (h >= 1.f); vk0 = s ? 0.f : h;
        bl = __ballot_sync(0xffffffffu, s); if (lane == 0) mkb[col16 + wid] = bl;
        p = ak1 * sk1 + bk1; h = vk1 + (p - vk1) * 0.5f; s = (h >= 1.f); vk1 = s ? 0.f : h;
        bl = __ballot_sync(0xffffffffu, s); if (lane == 0) mkb[col16 + 8 + wid] = bl;
        // v (+ float spikes to heads-layout output)
        p = av0 * sv0 + bv0; h = vv0 + (p - vv0) * 0.5f; s = (h >= 1.f); vv0 = s ? 0.f : h;
        float f0 = s ? 1.f : 0.f;
        bl = __ballot_sync(0xffffffffu, s); if (lane == 0) mv[col16 + wid] = bl;
        p = av1 * sv1 + bv1; h = vv1 + (p - vv1) * 0.5f; s = (h >= 1.f); vv1 = s ? 0.f : h;
        float f1 = s ? 1.f : 0.f;
        bl = __ballot_sync(0xffffffffu, s); if (lane == 0) mv[col16 + 8 + wid] = bl;
        if (write_v) {
            int hh = tid >> 6, d = tid & 63;
            int tb = t * 8 + b;
            vout[((size_t)(tb * 8 + hh) * 1024 + v) * 64 + d]     = f0;
            vout[((size_t)(tb * 8 + hh + 4) * 1024 + v) * 64 + d] = f1;
        }
    }
}

// ---------------- attn phase 1: attn[d][e] = popc sum over 2048 l ----------------
// one block per idx=(n_,b,h); bit-transpose via ballots, then 64x64 popcount dot.
__global__ __launch_bounds__(256)
void attn1_kernel(const uint32_t* __restrict__ mkb, const uint32_t* __restrict__ mv,
                  float* __restrict__ attn)
{
    int idx = blockIdx.x;
    int h = idx & 7, b = (idx >> 3) & 7, n_ = idx >> 6;
    __shared__ uint32_t Kw[64][65];
    __shared__ uint32_t Vw[64][65];
    int tid = threadIdx.x, wid = tid >> 5, lane = tid & 31;

    for (int chunk = wid; chunk < 64; chunk += 8) {
        int t = (n_ << 1) + (chunk >> 5);
        int nn = (chunk & 31) * 32 + lane;
        size_t col16 = ((size_t)((t * 8 + b) * 1024 + nn)) * 16;
        uint32_t k0 = mkb[col16 + 2 * h], k1 = mkb[col16 + 2 * h + 1];
        uint32_t v0 = mv[col16 + 2 * h],  v1 = mv[col16 + 2 * h + 1];
#pragma unroll
        for (int d = 0; d < 32; d++) {
            uint32_t bk = __ballot_sync(0xffffffffu, (k0 >> d) & 1);
            uint32_t bv = __ballot_sync(0xffffffffu, (v0 >> d) & 1);
            if (lane == 0) { Kw[d][chunk] = bk; Vw[d][chunk] = bv; }
        }
#pragma unroll
        for (int d = 0; d < 32; d++) {
            uint32_t bk = __ballot_sync(0xffffffffu, (k1 >> d) & 1);
            uint32_t bv = __ballot_sync(0xffffffffu, (v1 >> d) & 1);
            if (lane == 0) { Kw[32 + d][chunk] = bk; Vw[32 + d][chunk] = bv; }
        }
    }
    __syncthreads();

    int d = tid >> 2, eg = tid & 3;   // thread owns e = eg + 4j, j=0..15
    int acc[16];
#pragma unroll
    for (int j = 0; j < 16; j++) acc[j] = 0;
#pragma unroll 4
    for (int w = 0; w < 64; w++) {
        uint32_t kw = Kw[d][w];
#pragma unroll
        for (int j = 0; j < 16; j++)
            acc[j] += __popc(kw & Vw[eg + 4 * j][w]);
    }
    float* dst = attn + (size_t)idx * 4096 + d * 64 + eg;
#pragma unroll
    for (int j = 0; j < 16; j++)
        dst[4 * j] = (float)acc[j] * (1.0f / 1024.0f);
}

// ---------------- attn phase 2: out[l][e] = sum_{d: Q[l,d]=1} attn[d][e] ----------------
__global__ __launch_bounds__(256)
void attn2_kernel(const uint32_t* __restrict__ mq, const float* __restrict__ attn,
                  float* __restrict__ yT)
{
    int idx = blockIdx.y, lt = blockIdx.x;
    int h = idx & 7, b = (idx >> 3) & 7, n_ = idx >> 6;
    int t = (n_ << 1) + (lt >> 4);
    int nn0 = (lt & 15) << 6;

    __shared__ float Atn[64 * 65];
    int tid = threadIdx.x;
    const float* src = attn + (size_t)idx * 4096;
    for (int i = tid; i < 4096; i += 256)
        Atn[(i >> 6) * 65 + (i & 63)] = src[i];
    __syncthreads();

    int l = tid >> 2, e0 = (tid & 3) << 4;
    size_t col = (size_t)((t * 8 + b) * 1024 + nn0 + l);
    uint32_t q0 = mq[col * 16 + 2 * h], q1 = mq[col * 16 + 2 * h + 1];
    float acc[16];
#pragma unroll
    for (int j = 0; j < 16; j++) acc[j] = 0.f;
    while (q0) {
        int d = __ffs(q0) - 1; q0 &= q0 - 1;
        const float* a = Atn + d * 65 + e0;
#pragma unroll
        for (int j = 0; j < 16; j++) acc[j] += a[j];
    }
    while (q1) {
        int d = __ffs(q1) - 1 + 32; q1 &= q1 - 1;
        const float* a = Atn + d * 65 + e0;
#pragma unroll
        for (int j = 0; j < 16; j++) acc[j] += a[j];
    }
    float* dst = yT + col * 512 + h * 64 + e0;
#pragma unroll
    for (int j = 0; j < 16; j += 4)
        *(float4*)(dst + j) = make_float4(acc[j], acc[j + 1], acc[j + 2], acc[j + 3]);
}

// ---------------- Kernel B: fused attn-LIF + proj + residual + MLP ----------------
__global__ __launch_bounds__(256)
void pmlp_kernel(const float* __restrict__ yb, const float* __restrict__ xt,
                 const float* __restrict__ wp, const float* __restrict__ wf1,
                 const float* __restrict__ wf2,
                 const float* __restrict__ pwb, const float* __restrict__ ps, const float* __restrict__ psb,
                 const float* __restrict__ f1b, const float* __restrict__ f1s, const float* __restrict__ f1sb,
                 const float* __restrict__ f2b, const float* __restrict__ f2s, const float* __restrict__ f2sb,
                 float* __restrict__ f2o)
{
    int col = blockIdx.x;
    int b = col >> 10, v = col & 1023;
    int tid = threadIdx.x, wid = tid >> 5, lane = tid & 31;
    __shared__ uint32_t mpr[4][16];
    __shared__ uint32_t msk[64];
    __shared__ uint16_t lst[2048];
    __shared__ int base[65];

    // phase 1: LIF(0.5) on attention output
    {
        float v0 = 0.f, v1 = 0.f;
#pragma unroll
        for (int t = 0; t < 4; t++) {
            size_t ib = ((size_t)((t * 8 + b) * 1024 + v)) * 512;
            float x0 = yb[ib + tid], x1 = yb[ib + tid + 256];
            float h0 = v0 + (x0 - v0) * 0.5f, h1 = v1 + (x1 - v1) * 0.5f;
            bool s0 = (h0 >= 0.5f), s1 = (h1 >= 0.5f);
            v0 = s0 ? 0.f : h0; v1 = s1 ? 0.f : h1;
            uint32_t b0 = __ballot_sync(0xffffffffu, s0);
            uint32_t b1 = __ballot_sync(0xffffffffu, s1);
            if (lane == 0) { mpr[t][wid] = b0; mpr[t][8 + wid] = b1; }
        }
    }
    __syncthreads();

    float pwb0 = pwb[tid], pwb1 = pwb[tid + 256];
    float ps0  = ps[tid],  ps1  = ps[tid + 256];
    float psb0 = psb[tid], psb1 = psb[tid + 256];
    float f2b0 = f2b[tid], f2b1 = f2b[tid + 256];
    float f2s0 = f2s[tid], f2s1 = f2s[tid + 256];
    float f2q0 = f2sb[tid], f2q1 = f2sb[tid + 256];
    float f1bb[8], f1ss[8], f1qq[8];
#pragma unroll
    for (int r = 0; r < 8; r++) {
        int c = tid + 256 * r;
        f1bb[r] = f1b[c]; f1ss[r] = f1s[c]; f1qq[r] = f1sb[c];
    }

    float vxa0 = 0.f, vxa1 = 0.f;
    float vh[8];
#pragma unroll
    for (int r = 0; r < 8; r++) vh[r] = 0.f;

#pragma unroll 1
    for (int t = 0; t < 4; t++) {
        // --- proj: build list + gather (unroll 4) ---
        if (tid == 0) {
            int s = 0;
#pragma unroll
            for (int w = 0; w < 16; w++) { base[w] = s; s += __popc(mpr[t][w]); }
            base[16] = s;
        }
        __syncthreads();
        if (tid < 16) {
            uint32_t m = mpr[t][tid];
            int off = base[tid];
            while (m) { int bi = __ffs(m) - 1; m &= m - 1; lst[off++] = (uint16_t)(tid * 32 + bi); }
        }
        __syncthreads();
        int n = base[16];
        float a0 = 0.f, a1 = 0.f;
        int i = 0;
        for (; i + 4 <= n; i += 4) {
            const float* r0 = wp + (size_t)lst[i] * 512;
            const float* r1 = wp + (size_t)lst[i + 1] * 512;
            const float* r2 = wp + (size_t)lst[i + 2] * 512;
            const float* r3 = wp + (size_t)lst[i + 3] * 512;
            float u0 = r0[tid], u1 = r0[tid + 256];
            float u2 = r1[tid], u3 = r1[tid + 256];
            float u4 = r2[tid], u5 = r2[tid + 256];
            float u6 = r3[tid], u7 = r3[tid + 256];
            a0 += u0; a1 += u1; a0 += u2; a1 += u3;
            a0 += u4; a1 += u5; a0 += u6; a1 += u7;
        }
        for (; i < n; i++) {
            const float* r0 = wp + (size_t)lst[i] * 512;
            a0 += r0[tid]; a1 += r0[tid + 256];
        }
        size_t ib = ((size_t)((t * 8 + b) * 1024 + v)) * 512;
        float xa0 = (a0 + pwb0) * ps0 + psb0 + xt[ib + tid];
        float xa1 = (a1 + pwb1) * ps1 + psb1 + xt[ib + tid + 256];

        // LIF(1.0) -> m1 masks
        {
            float h0 = vxa0 + (xa0 - vxa0) * 0.5f, h1 = vxa1 + (xa1 - vxa1) * 0.5f;
            bool s0 = (h0 >= 1.f), s1 = (h1 >= 1.f);
            vxa0 = s0 ? 0.f : h0; vxa1 = s1 ? 0.f : h1;
            uint32_t b0 = __ballot_sync(0xffffffffu, s0);
            uint32_t b1 = __ballot_sync(0xffffffffu, s1);
            if (lane == 0) { msk[wid] = b0; msk[8 + wid] = b1; }
        }
        __syncthreads();

        // --- fc1: build list + gather (unroll 2, 8 rows each) ---
        if (tid == 0) {
            int s = 0;
#pragma unroll
            for (int w = 0; w < 16; w++) { base[w] = s; s += __popc(msk[w]); }
            base[16] = s;
        }
        __syncthreads();
        if (tid < 16) {
            uint32_t m = msk[tid];
            int off = base[tid];
            while (m) { int bi = __ffs(m) - 1; m &= m - 1; lst[off++] = (uint16_t)(tid * 32 + bi); }
        }
        __syncthreads();
        n = base[16];
        float ha[8];
#pragma unroll
        for (int r = 0; r < 8; r++) ha[r] = 0.f;
        i = 0;
        for (; i + 2 <= n; i += 2) {
            const float* r0 = wf1 + (size_t)lst[i] * 2048 + tid;
            const float* r1 = wf1 + (size_t)lst[i + 1] * 2048 + tid;
            float u0[8], u1[8];
#pragma unroll
            for (int r = 0; r < 8; r++) u0[r] = r0[r * 256];
#pragma unroll
            for (int r = 0; r < 8; r++) u1[r] = r1[r * 256];
#pragma unroll
            for (int r = 0; r < 8; r++) { ha[r] += u0[r]; ha[r] += u1[r]; }
        }
        if (i < n) {
            const float* r0 = wf1 + (size_t)lst[i] * 2048 + tid;
#pragma unroll
            for (int r = 0; r < 8; r++) ha[r] += r0[r * 256];
        }

        // BN + LIF(1.0) -> hid masks
#pragma unroll
        for (int r = 0; r < 8; r++) {
            float hv = (ha[r] + f1bb[r]) * f1ss[r] + f1qq[r];
            float h = vh[r] + (hv - vh[r]) * 0.5f;
            bool s = (h >= 1.f);
            vh[r] = s ? 0.f : h;
            uint32_t m = __ballot_sync(0xffffffffu, s);
            if (lane == 0) msk[8 * r + wid] = m;
        }
        __syncthreads();

        // --- fc2: build list (64 words) + gather (unroll 4) ---
        if (tid == 0) {
            int s = 0;
            for (int w = 0; w < 64; w++) { base[w] = s; s += __popc(msk[w]); }
            base[64] = s;
        }
        __syncthreads();
        if (tid < 64) {
            uint32_t m = msk[tid];
            int off = base[tid];
            while (m) { int bi = __ffs(m) - 1; m &= m - 1; lst[off++] = (uint16_t)(tid * 32 + bi); }
        }
        __syncthreads();
        n = base[64];
        float f0 = 0.f, f1 = 0.f;
        i = 0;
        for (; i + 4 <= n; i += 4) {
            const float* r0 = wf2 + (size_t)lst[i] * 512;
            const float* r1 = wf2 + (size_t)lst[i + 1] * 512;
            const float* r2 = wf2 + (size_t)lst[i + 2] * 512;
            const float* r3 = wf2 + (size_t)lst[i + 3] * 512;
            float u0 = r0[tid], u1 = r0[tid + 256];
            float u2 = r1[tid], u3 = r1[tid + 256];
            float u4 = r2[tid], u5 = r2[tid + 256];
            float u6 = r3[tid], u7 = r3[tid + 256];
            f0 += u0; f1 += u1; f0 += u2; f1 += u3;
            f0 += u4; f1 += u5; f0 += u6; f1 += u7;
        }
        for (; i < n; i++) {
            const float* r0 = wf2 + (size_t)lst[i] * 512;
            f0 += r0[tid]; f1 += r0[tid + 256];
        }
        f2o[ib + tid]       = (f0 + f2b0) * f2s0 + f2q0 + xa0;
        f2o[ib + tid + 256] = (f1 + f2b1) * f2s1 + f2q1 + xa1;
        __syncthreads();
    }
}

// ---------------- host launcher ----------------
extern "C" void kernel_launch(void* const* d_in, const int* in_sizes, int n_in,
                              void* d_out, int out_size)
{
    const float* x    = (const float*)d_in[0];
    const float* qw   = (const float*)d_in[1];
    const float* qs   = (const float*)d_in[2];
    const float* qb   = (const float*)d_in[3];
    const float* kw   = (const float*)d_in[4];
    const float* ks_  = (const float*)d_in[5];
    const float* kb   = (const float*)d_in[6];
    const float* vw   = (const float*)d_in[7];
    const float* vs   = (const float*)d_in[8];
    const float* vb   = (const float*)d_in[9];
    const float* pw   = (const float*)d_in[10];
    const float* pwb  = (const float*)d_in[11];
    const float* ps   = (const float*)d_in[12];
    const float* psb  = (const float*)d_in[13];
    const float* f1w  = (const float*)d_in[14];
    const float* f1b  = (const float*)d_in[15];
    const float* f1s  = (const float*)d_in[16];
    const float* f1sb = (const float*)d_in[17];
    const float* f2w  = (const float*)d_in[18];
    const float* f2b  = (const float*)d_in[19];
    const float* f2s  = (const float*)d_in[20];
    const float* f2sb = (const float*)d_in[21];

    float *xt, *yb, *f2o, *wqkv, *wp, *wf1, *wf2, *attn;
    uint32_t *mq, *mkb, *mv;
    cudaGetSymbolAddress((void**)&xt,   g_xt);
    cudaGetSymbolAddress((void**)&yb,   g_y);
    cudaGetSymbolAddress((void**)&f2o,  g_f2);
    cudaGetSymbolAddress((void**)&wqkv, g_wqkv);
    cudaGetSymbolAddress((void**)&wp,   g_wp);
    cudaGetSymbolAddress((void**)&wf1,  g_wf1);
    cudaGetSymbolAddress((void**)&wf2,  g_wf2);
    cudaGetSymbolAddress((void**)&attn, g_attn);
    cudaGetSymbolAddress((void**)&mq,   g_mq);
    cudaGetSymbolAddress((void**)&mkb,  g_mk);
    cudaGetSymbolAddress((void**)&mv,   g_mv);

    float* out = (float*)d_out;
    int write_v = (out_size >= 2 * MAIN_ELEMS);
    float* vout = write_v ? (out + MAIN_ELEMS) : f2o;

    dim3 tb32(32, 8);
    qkvw_kern<<<dim3(CC / 32, CC / 32, 3), tb32>>>(qw, kw, vw, wqkv);
    tkern<<<dim3(CC / 32, CC / 32, 1), tb32>>>(pw,  wp,  CC,  CC);
    tkern<<<dim3(CC / 32, HID / 32, 1), tb32>>>(f1w, wf1, HID, CC);
    tkern<<<dim3(HID / 32, CC / 32, 1), tb32>>>(f2w, wf2, CC,  HID);

    // x -> [tb][v][c]
    tkern<<<dim3(VV / 32, CC / 32, NTB), tb32>>>(x, xt, CC, VV);

    // fused shortcut-LIF + qkv + qkv-LIF -> bitmasks (+ v float out)
    qkv_kernel<<<NBV, 256>>>(xt, wqkv, mq, mkb, mv, vout, write_v,
                             qs, qb, ks_, kb, vs, vb);

    // bit-domain attention
    attn1_kernel<<<128, 256>>>(mkb, mv, attn);
    attn2_kernel<<<dim3(32, 128), 256>>>(mq, attn, yb);

    // fused attn-LIF + proj + residual + MLP
    pmlp_kernel<<<NBV, 256>>>(yb, xt, wp, wf1, wf2,
                              pwb, ps, psb, f1b, f1s, f1sb, f2b, f2s, f2sb, f2o);

    // main output: transpose back to (T,B,C,V)
    tkern<<<dim3(CC / 32, VV / 32, NTB), tb32>>>(f2o, out, VV, CC);
}

// round 5
// speedup vs baseline: 7.1439x; 1.0220x over previous
#include <cuda_runtime.h>
#include <cstddef>
#include <cstdint>

// ---------------- problem constants ----------------
#define TT   4
#define BB   8
#define CC   512
#define VV   1024
#define HID  2048
#define NTB  (TT*BB)              // 32
#define MAIN_ELEMS (TT*BB*CC*VV)  // 16,777,216
#define NBV  (BB*VV)              // 8192 (b,v) columns

// ---------------- scratch ----------------
__device__ float g_xt[MAIN_ELEMS];      // x transposed [tb][v][c]
__device__ float g_y [MAIN_ELEMS];      // attention output (pre-LIF) [tb][v][c]
__device__ float g_f2[MAIN_ELEMS];      // final sum, transposed [tb][v][c]
__device__ float g_wqkv[CC*3*CC];       // [k][q512|k512|v512]
__device__ float g_wp [CC*CC];
__device__ float g_wf1[CC*HID];
__device__ float g_wf2[HID*CC];
__device__ uint32_t g_mq[NTB*VV*16];    // spike bitmasks: [tb*1024+v][16 words]
__device__ uint32_t g_mk[NTB*VV*16];
__device__ uint32_t g_mv[NTB*VV*16];
__device__ float g_attn[128*4096];      // per (n_,b,h): 64x64 attn matrix

// mask word from 4 spike bits per thread, 8-lane groups (channels = 4*lane_in_grp + bit)
__device__ __forceinline__ void put_word4(uint32_t nib, int lane, uint32_t* dst)
{
    uint32_t gm = 0xFFu << (8 * (lane >> 3));
    uint32_t wd = __reduce_or_sync(gm, nib << ((lane & 7) * 4));
    if ((lane & 7) == 0) dst[lane >> 3] = wd;
}
// mask word from 2 spike bits per thread, 16-lane groups
__device__ __forceinline__ void put_word2(uint32_t pr, int lane, uint32_t* dst)
{
    uint32_t gm = 0xFFFFu << (16 * (lane >> 4));
    uint32_t wd = __reduce_or_sync(gm, pr << ((lane & 15) * 2));
    if ((lane & 15) == 0) dst[lane >> 4] = wd;
}

// ---------------- 32x32 tiled transpose: out[z][c][r] = in[z][r][c] ----------------
__global__ void tkern(const float* __restrict__ in, float* __restrict__ out,
                      int R, int Cn)
{
    __shared__ float t[32][33];
    size_t bs = (size_t)R * Cn * blockIdx.z;
    int r0 = blockIdx.y * 32, c0 = blockIdx.x * 32;
    int tx = threadIdx.x, ty = threadIdx.y;
#pragma unroll
    for (int j = 0; j < 4; j++)
        t[ty + 8 * j][tx] = in[bs + (size_t)(r0 + ty + 8 * j) * Cn + c0 + tx];
    __syncthreads();
#pragma unroll
    for (int j = 0; j < 4; j++)
        out[bs + (size_t)(c0 + ty + 8 * j) * R + r0 + tx] = t[tx][ty + 8 * j];
}

// ---------------- interleaved qkv weight transpose ----------------
__global__ void qkvw_kern(const float* __restrict__ qw, const float* __restrict__ kw,
                          const float* __restrict__ vw, float* __restrict__ wqkv)
{
    __shared__ float t[32][33];
    const float* src = (blockIdx.z == 0) ? qw : (blockIdx.z == 1) ? kw : vw;
    int m0 = blockIdx.y * 32, k0 = blockIdx.x * 32;
    int tx = threadIdx.x, ty = threadIdx.y;
#pragma unroll
    for (int j = 0; j < 4; j++)
        t[ty + 8 * j][tx] = src[(size_t)(m0 + ty + 8 * j) * CC + k0 + tx];
    __syncthreads();
#pragma unroll
    for (int j = 0; j < 4; j++)
        wqkv[(size_t)(k0 + ty + 8 * j) * 1536 + blockIdx.z * 512 + m0 + tx] = t[tx][ty + 8 * j];
}

// ---------------- Kernel A: fused shortcut-LIF + qkv conv/BN + qkv-LIF -> bitmasks ----
// threads 0-127 own q-channels 4tid..4tid+3; threads 128-255 own k-channels 4(tid-128)..;
// all threads own v-channels 2tid,2tid+1.
__global__ __launch_bounds__(256)
void qkv_kernel(const float* __restrict__ xt, const float* __restrict__ wqkv,
                uint32_t* __restrict__ mq, uint32_t* __restrict__ mkb,
                uint32_t* __restrict__ mv,
                float* __restrict__ vout, int write_v,
                const float* __restrict__ qs, const float* __restrict__ qb,
                const float* __restrict__ ks_, const float* __restrict__ kb,
                const float* __restrict__ vs, const float* __restrict__ vb)
{
    int col = blockIdx.x;
    int b = col >> 10, v = col & 1023;
    int tid = threadIdx.x, wid = tid >> 5, lane = tid & 31;
    __shared__ uint32_t mx[4][16];
    __shared__ uint16_t lst[4][512];
    __shared__ int base[4][17];

    // phase 1: LIF(1.0) on x -> masks (channels 2tid, 2tid+1)
    {
        float v0 = 0.f, v1 = 0.f;
#pragma unroll
        for (int t = 0; t < 4; t++) {
            size_t ib = ((size_t)((t * 8 + b) * 1024 + v)) * 512;
            float2 xv = *(const float2*)(xt + ib + 2 * tid);
            float h0 = v0 + (xv.x - v0) * 0.5f, h1 = v1 + (xv.y - v1) * 0.5f;
            uint32_t s0 = (h0 >= 1.f), s1 = (h1 >= 1.f);
            v0 = s0 ? 0.f : h0; v1 = s1 ? 0.f : h1;
            put_word2(s0 | (s1 << 1), lane, &mx[t][2 * wid]);
        }
    }
    __syncthreads();
    // build index lists (deterministic order)
    if (tid < 4) {
        int s = 0;
#pragma unroll
        for (int w = 0; w < 16; w++) { base[tid][w] = s; s += __popc(mx[tid][w]); }
        base[tid][16] = s;
    }
    __syncthreads();
    if (tid < 64) {
        int t = tid >> 4, w = tid & 15;
        uint32_t m = mx[t][w];
        int off = base[t][w];
        while (m) { int bi = __ffs(m) - 1; m &= m - 1; lst[t][off++] = (uint16_t)(w * 32 + bi); }
    }
    __syncthreads();

    // BN params: q or k (4 ch) + v (2 ch)
    float4 sc4, bc4;
    if (tid < 128) {
        sc4 = *(const float4*)(qs + 4 * tid);
        bc4 = *(const float4*)(qb + 4 * tid);
    } else {
        sc4 = *(const float4*)(ks_ + 4 * (tid - 128));
        bc4 = *(const float4*)(kb + 4 * (tid - 128));
    }
    float2 sv2 = *(const float2*)(vs + 2 * tid);
    float2 bv2 = *(const float2*)(vb + 2 * tid);

    float m0 = 0.f, m1 = 0.f, m2 = 0.f, m3 = 0.f;   // q or k membranes
    float mv0 = 0.f, mv1 = 0.f;                      // v membranes

#pragma unroll 1
    for (int t = 0; t < 4; t++) {
        float a0 = 0.f, a1 = 0.f, a2 = 0.f, a3 = 0.f;
        float av0 = 0.f, av1 = 0.f;
        int n = base[t][16];
        int i = 0;
        for (; i + 2 <= n; i += 2) {
            const float* r0 = wqkv + (size_t)lst[t][i] * 1536;
            const float* r1 = wqkv + (size_t)lst[t][i + 1] * 1536;
            float4 u0 = *(const float4*)(r0 + 4 * tid);
            float2 w0 = *(const float2*)(r0 + 1024 + 2 * tid);
            float4 u1 = *(const float4*)(r1 + 4 * tid);
            float2 w1 = *(const float2*)(r1 + 1024 + 2 * tid);
            a0 += u0.x; a1 += u0.y; a2 += u0.z; a3 += u0.w; av0 += w0.x; av1 += w0.y;
            a0 += u1.x; a1 += u1.y; a2 += u1.z; a3 += u1.w; av0 += w1.x; av1 += w1.y;
        }
        if (i < n) {
            const float* r0 = wqkv + (size_t)lst[t][i] * 1536;
            float4 u0 = *(const float4*)(r0 + 4 * tid);
            float2 w0 = *(const float2*)(r0 + 1024 + 2 * tid);
            a0 += u0.x; a1 += u0.y; a2 += u0.z; a3 += u0.w; av0 += w0.x; av1 += w0.y;
        }

        size_t col16 = ((size_t)((t * 8 + b) * 1024 + v)) * 16;
        // q or k: 4 channels
        {
            float p, h;
            uint32_t s0, s1, s2, s3;
            p = a0 * sc4.x + bc4.x; h = m0 + (p - m0) * 0.5f; s0 = (h >= 1.f); m0 = s0 ? 0.f : h;
            p = a1 * sc4.y + bc4.y; h = m1 + (p - m1) * 0.5f; s1 = (h >= 1.f); m1 = s1 ? 0.f : h;
            p = a2 * sc4.z + bc4.z; h = m2 + (p - m2) * 0.5f; s2 = (h >= 1.f); m2 = s2 ? 0.f : h;
            p = a3 * sc4.w + bc4.w; h = m3 + (p - m3) * 0.5f; s3 = (h >= 1.f); m3 = s3 ? 0.f : h;
            uint32_t nib = s0 | (s1 << 1) | (s2 << 2) | (s3 << 3);
            if (wid < 4) put_word4(nib, lane, mq + col16 + 4 * wid);
            else         put_word4(nib, lane, mkb + col16 + 4 * (wid - 4));
        }
        // v: 2 channels (+ float spikes into heads-layout output)
        {
            float p, h;
            p = av0 * sv2.x + bv2.x; h = mv0 + (p - mv0) * 0.5f;
            uint32_t s0 = (h >= 1.f); mv0 = s0 ? 0.f : h;
            p = av1 * sv2.y + bv2.y; h = mv1 + (p - mv1) * 0.5f;
            uint32_t s1 = (h >= 1.f); mv1 = s1 ? 0.f : h;
            put_word2(s0 | (s1 << 1), lane, mv + col16 + 2 * wid);
            if (write_v) {
                int c0 = 2 * tid;
                int hh = c0 >> 6, d = c0 & 63;
                int tb = t * 8 + b;
                float2 f = make_float2(s0 ? 1.f : 0.f, s1 ? 1.f : 0.f);
                *(float2*)(vout + ((size_t)(tb * 8 + hh) * 1024 + v) * 64 + d) = f;
            }
        }
    }
}

// ---------------- attn phase 1: attn[d][e] = popc sum over 2048 l ----------------
__global__ __launch_bounds__(256)
void attn1_kernel(const uint32_t* __restrict__ mkb, const uint32_t* __restrict__ mv,
                  float* __restrict__ attn)
{
    int idx = blockIdx.x;
    int h = idx & 7, b = (idx >> 3) & 7, n_ = idx >> 6;
    __shared__ uint32_t Kw[64][65];
    __shared__ uint32_t Vw[64][65];
    int tid = threadIdx.x, wid = tid >> 5, lane = tid & 31;

    for (int chunk = wid; chunk < 64; chunk += 8) {
        int t = (n_ << 1) + (chunk >> 5);
        int nn = (chunk & 31) * 32 + lane;
        size_t col16 = ((size_t)((t * 8 + b) * 1024 + nn)) * 16;
        uint32_t k0 = mkb[col16 + 2 * h], k1 = mkb[col16 + 2 * h + 1];
        uint32_t v0 = mv[col16 + 2 * h],  v1 = mv[col16 + 2 * h + 1];
#pragma unroll
        for (int d = 0; d < 32; d++) {
            uint32_t bk = __ballot_sync(0xffffffffu, (k0 >> d) & 1);
            uint32_t bv = __ballot_sync(0xffffffffu, (v0 >> d) & 1);
            if (lane == 0) { Kw[d][chunk] = bk; Vw[d][chunk] = bv; }
        }
#pragma unroll
        for (int d = 0; d < 32; d++) {
            uint32_t bk = __ballot_sync(0xffffffffu, (k1 >> d) & 1);
            uint32_t bv = __ballot_sync(0xffffffffu, (v1 >> d) & 1);
            if (lane == 0) { Kw[32 + d][chunk] = bk; Vw[32 + d][chunk] = bv; }
        }
    }
    __syncthreads();

    int d = tid >> 2, eg = tid & 3;
    int acc[16];
#pragma unroll
    for (int j = 0; j < 16; j++) acc[j] = 0;
#pragma unroll 4
    for (int w = 0; w < 64; w++) {
        uint32_t kw = Kw[d][w];
#pragma unroll
        for (int j = 0; j < 16; j++)
            acc[j] += __popc(kw & Vw[eg + 4 * j][w]);
    }
    float* dst = attn + (size_t)idx * 4096 + d * 64 + eg;
#pragma unroll
    for (int j = 0; j < 16; j++)
        dst[4 * j] = (float)acc[j] * (1.0f / 1024.0f);
}

// ---------------- attn phase 2: out[l][e] = sum_{d: Q[l,d]=1} attn[d][e] ----------------
__global__ __launch_bounds__(256)
void attn2_kernel(const uint32_t* __restrict__ mq, const float* __restrict__ attn,
                  float* __restrict__ yT)
{
    int idx = blockIdx.y, lt = blockIdx.x;
    int h = idx & 7, b = (idx >> 3) & 7, n_ = idx >> 6;
    int t = (n_ << 1) + (lt >> 4);
    int nn0 = (lt & 15) << 6;

    __shared__ float Atn[64 * 65];
    int tid = threadIdx.x;
    const float* src = attn + (size_t)idx * 4096;
    for (int i = tid; i < 4096; i += 256)
        Atn[(i >> 6) * 65 + (i & 63)] = src[i];
    __syncthreads();

    int l = tid >> 2, e0 = (tid & 3) << 4;
    size_t col = (size_t)((t * 8 + b) * 1024 + nn0 + l);
    uint32_t q0 = mq[col * 16 + 2 * h], q1 = mq[col * 16 + 2 * h + 1];
    float acc[16];
#pragma unroll
    for (int j = 0; j < 16; j++) acc[j] = 0.f;
    while (q0) {
        int d = __ffs(q0) - 1; q0 &= q0 - 1;
        const float* a = Atn + d * 65 + e0;
#pragma unroll
        for (int j = 0; j < 16; j++) acc[j] += a[j];
    }
    while (q1) {
        int d = __ffs(q1) - 1 + 32; q1 &= q1 - 1;
        const float* a = Atn + d * 65 + e0;
#pragma unroll
        for (int j = 0; j < 16; j++) acc[j] += a[j];
    }
    float* dst = yT + col * 512 + h * 64 + e0;
#pragma unroll
    for (int j = 0; j < 16; j += 4)
        *(float4*)(dst + j) = make_float4(acc[j], acc[j + 1], acc[j + 2], acc[j + 3]);
}

// ---------------- Kernel B: fused attn-LIF + proj + residual + MLP ----------------
// proj/fc2 channels: thread owns {2tid, 2tid+1}. fc1 hidden: {4tid..4tid+3, 1024+4tid..+3}
__global__ __launch_bounds__(256)
void pmlp_kernel(const float* __restrict__ yb, const float* __restrict__ xt,
                 const float* __restrict__ wp, const float* __restrict__ wf1,
                 const float* __restrict__ wf2,
                 const float* __restrict__ pwb, const float* __restrict__ ps, const float* __restrict__ psb,
                 const float* __restrict__ f1b, const float* __restrict__ f1s, const float* __restrict__ f1sb,
                 const float* __restrict__ f2b, const float* __restrict__ f2s, const float* __restrict__ f2sb,
                 float* __restrict__ f2o)
{
    int col = blockIdx.x;
    int b = col >> 10, v = col & 1023;
    int tid = threadIdx.x, wid = tid >> 5, lane = tid & 31;
    __shared__ uint32_t mpr[4][16];
    __shared__ uint32_t msk[64];
    __shared__ uint16_t lst[2048];
    __shared__ int base[65];

    // phase 1: LIF(0.5) on attention output (channels 2tid, 2tid+1)
    {
        float v0 = 0.f, v1 = 0.f;
#pragma unroll
        for (int t = 0; t < 4; t++) {
            size_t ib = ((size_t)((t * 8 + b) * 1024 + v)) * 512;
            float2 yv = *(const float2*)(yb + ib + 2 * tid);
            float h0 = v0 + (yv.x - v0) * 0.5f, h1 = v1 + (yv.y - v1) * 0.5f;
            uint32_t s0 = (h0 >= 0.5f), s1 = (h1 >= 0.5f);
            v0 = s0 ? 0.f : h0; v1 = s1 ? 0.f : h1;
            put_word2(s0 | (s1 << 1), lane, &mpr[t][2 * wid]);
        }
    }
    __syncthreads();

    float2 pwb2 = *(const float2*)(pwb + 2 * tid);
    float2 ps2  = *(const float2*)(ps + 2 * tid);
    float2 psb2 = *(const float2*)(psb + 2 * tid);
    float2 f2b2 = *(const float2*)(f2b + 2 * tid);
    float2 f2s2 = *(const float2*)(f2s + 2 * tid);
    float2 f2q2 = *(const float2*)(f2sb + 2 * tid);
    float4 f1b4a = *(const float4*)(f1b + 4 * tid), f1b4b = *(const float4*)(f1b + 1024 + 4 * tid);
    float4 f1s4a = *(const float4*)(f1s + 4 * tid), f1s4b = *(const float4*)(f1s + 1024 + 4 * tid);
    float4 f1q4a = *(const float4*)(f1sb + 4 * tid), f1q4b = *(const float4*)(f1sb + 1024 + 4 * tid);

    float vxa0 = 0.f, vxa1 = 0.f;
    float vh[8];
#pragma unroll
    for (int r = 0; r < 8; r++) vh[r] = 0.f;

#pragma unroll 1
    for (int t = 0; t < 4; t++) {
        // --- proj: build list + gather (float2, unroll 4) ---
        if (tid == 0) {
            int s = 0;
#pragma unroll
            for (int w = 0; w < 16; w++) { base[w] = s; s += __popc(mpr[t][w]); }
            base[16] = s;
        }
        __syncthreads();
        if (tid < 16) {
            uint32_t m = mpr[t][tid];
            int off = base[tid];
            while (m) { int bi = __ffs(m) - 1; m &= m - 1; lst[off++] = (uint16_t)(tid * 32 + bi); }
        }
        __syncthreads();
        int n = base[16];
        float a0 = 0.f, a1 = 0.f;
        int i = 0;
        for (; i + 4 <= n; i += 4) {
            float2 u0 = *(const float2*)(wp + (size_t)lst[i] * 512 + 2 * tid);
            float2 u1 = *(const float2*)(wp + (size_t)lst[i + 1] * 512 + 2 * tid);
            float2 u2 = *(const float2*)(wp + (size_t)lst[i + 2] * 512 + 2 * tid);
            float2 u3 = *(const float2*)(wp + (size_t)lst[i + 3] * 512 + 2 * tid);
            a0 += u0.x; a1 += u0.y; a0 += u1.x; a1 += u1.y;
            a0 += u2.x; a1 += u2.y; a0 += u3.x; a1 += u3.y;
        }
        for (; i < n; i++) {
            float2 u0 = *(const float2*)(wp + (size_t)lst[i] * 512 + 2 * tid);
            a0 += u0.x; a1 += u0.y;
        }
        size_t ib = ((size_t)((t * 8 + b) * 1024 + v)) * 512;
        float2 xres = *(const float2*)(xt + ib + 2 * tid);
        float xa0 = (a0 + pwb2.x) * ps2.x + psb2.x + xres.x;
        float xa1 = (a1 + pwb2.y) * ps2.y + psb2.y + xres.y;

        // LIF(1.0) -> m1 masks
        {
            float h0 = vxa0 + (xa0 - vxa0) * 0.5f, h1 = vxa1 + (xa1 - vxa1) * 0.5f;
            uint32_t s0 = (h0 >= 1.f), s1 = (h1 >= 1.f);
            vxa0 = s0 ? 0.f : h0; vxa1 = s1 ? 0.f : h1;
            put_word2(s0 | (s1 << 1), lane, &msk[2 * wid]);
        }
        __syncthreads();

        // --- fc1: build list + gather (2x float4, unroll 2) ---
        if (tid == 0) {
            int s = 0;
#pragma unroll
            for (int w = 0; w < 16; w++) { base[w] = s; s += __popc(msk[w]); }
            base[16] = s;
        }
        __syncthreads();
        if (tid < 16) {
            uint32_t m = msk[tid];
            int off = base[tid];
            while (m) { int bi = __ffs(m) - 1; m &= m - 1; lst[off++] = (uint16_t)(tid * 32 + bi); }
        }
        __syncthreads();
        n = base[16];
        float ha[8];
#pragma unroll
        for (int r = 0; r < 8; r++) ha[r] = 0.f;
        i = 0;
        for (; i + 2 <= n; i += 2) {
            const float* r0 = wf1 + (size_t)lst[i] * 2048;
            const float* r1 = wf1 + (size_t)lst[i + 1] * 2048;
            float4 u0 = *(const float4*)(r0 + 4 * tid);
            float4 u1 = *(const float4*)(r0 + 1024 + 4 * tid);
            float4 u2 = *(const float4*)(r1 + 4 * tid);
            float4 u3 = *(const float4*)(r1 + 1024 + 4 * tid);
            ha[0] += u0.x; ha[1] += u0.y; ha[2] += u0.z; ha[3] += u0.w;
            ha[4] += u1.x; ha[5] += u1.y; ha[6] += u1.z; ha[7] += u1.w;
            ha[0] += u2.x; ha[1] += u2.y; ha[2] += u2.z; ha[3] += u2.w;
            ha[4] += u3.x; ha[5] += u3.y; ha[6] += u3.z; ha[7] += u3.w;
        }
        if (i < n) {
            const float* r0 = wf1 + (size_t)lst[i] * 2048;
            float4 u0 = *(const float4*)(r0 + 4 * tid);
            float4 u1 = *(const float4*)(r0 + 1024 + 4 * tid);
            ha[0] += u0.x; ha[1] += u0.y; ha[2] += u0.z; ha[3] += u0.w;
            ha[4] += u1.x; ha[5] += u1.y; ha[6] += u1.z; ha[7] += u1.w;
        }

        // BN + LIF(1.0) -> hid masks (ch 4tid.. and 1024+4tid..)
        {
            float p, h;
            uint32_t s0, s1, s2, s3;
            p = (ha[0] + f1b4a.x) * f1s4a.x + f1q4a.x; h = vh[0] + (p - vh[0]) * 0.5f; s0 = (h >= 1.f); vh[0] = s0 ? 0.f : h;
            p = (ha[1] + f1b4a.y) * f1s4a.y + f1q4a.y; h = vh[1] + (p - vh[1]) * 0.5f; s1 = (h >= 1.f); vh[1] = s1 ? 0.f : h;
            p = (ha[2] + f1b4a.z) * f1s4a.z + f1q4a.z; h = vh[2] + (p - vh[2]) * 0.5f; s2 = (h >= 1.f); vh[2] = s2 ? 0.f : h;
            p = (ha[3] + f1b4a.w) * f1s4a.w + f1q4a.w; h = vh[3] + (p - vh[3]) * 0.5f; s3 = (h >= 1.f); vh[3] = s3 ? 0.f : h;
            put_word4(s0 | (s1 << 1) | (s2 << 2) | (s3 << 3), lane, msk + 4 * wid);
            p = (ha[4] + f1b4b.x) * f1s4b.x + f1q4b.x; h = vh[4] + (p - vh[4]) * 0.5f; s0 = (h >= 1.f); vh[4] = s0 ? 0.f : h;
            p = (ha[5] + f1b4b.y) * f1s4b.y + f1q4b.y; h = vh[5] + (p - vh[5]) * 0.5f; s1 = (h >= 1.f); vh[5] = s1 ? 0.f : h;
            p = (ha[6] + f1b4b.z) * f1s4b.z + f1q4b.z; h = vh[6] + (p - vh[6]) * 0.5f; s2 = (h >= 1.f); vh[6] = s2 ? 0.f : h;
            p = (ha[7] + f1b4b.w) * f1s4b.w + f1q4b.w; h = vh[7] + (p - vh[7]) * 0.5f; s3 = (h >= 1.f); vh[7] = s3 ? 0.f : h;
            put_word4(s0 | (s1 << 1) | (s2 << 2) | (s3 << 3), lane, msk + 32 + 4 * wid);
        }
        __syncthreads();

        // --- fc2: build list (64 words) + gather (float2, unroll 4) ---
        if (tid == 0) {
            int s = 0;
            for (int w = 0; w < 64; w++) { base[w] = s; s += __popc(msk[w]); }
            base[64] = s;
        }
        __syncthreads();
        if (tid < 64) {
            uint32_t m = msk[tid];
            int off = base[tid];
            while (m) { int bi = __ffs(m) - 1; m &= m - 1; lst[off++] = (uint16_t)(tid * 32 + bi); }
        }
        __syncthreads();
        n = base[64];
        float f0 = 0.f, f1 = 0.f;
        i = 0;
        for (; i + 4 <= n; i += 4) {
            float2 u0 = *(const float2*)(wf2 + (size_t)lst[i] * 512 + 2 * tid);
            float2 u1 = *(const float2*)(wf2 + (size_t)lst[i + 1] * 512 + 2 * tid);
            float2 u2 = *(const float2*)(wf2 + (size_t)lst[i + 2] * 512 + 2 * tid);
            float2 u3 = *(const float2*)(wf2 + (size_t)lst[i + 3] * 512 + 2 * tid);
            f0 += u0.x; f1 += u0.y; f0 += u1.x; f1 += u1.y;
            f0 += u2.x; f1 += u2.y; f0 += u3.x; f1 += u3.y;
        }
        for (; i < n; i++) {
            float2 u0 = *(const float2*)(wf2 + (size_t)lst[i] * 512 + 2 * tid);
            f0 += u0.x; f1 += u0.y;
        }
        float2 o;
        o.x = (f0 + f2b2.x) * f2s2.x + f2q2.x + xa0;
        o.y = (f1 + f2b2.y) * f2s2.y + f2q2.y + xa1;
        *(float2*)(f2o + ib + 2 * tid) = o;
        __syncthreads();
    }
}

// ---------------- host launcher ----------------
extern "C" void kernel_launch(void* const* d_in, const int* in_sizes, int n_in,
                              void* d_out, int out_size)
{
    const float* x    = (const float*)d_in[0];
    const float* qw   = (const float*)d_in[1];
    const float* qs   = (const float*)d_in[2];
    const float* qb   = (const float*)d_in[3];
    const float* kw   = (const float*)d_in[4];
    const float* ks_  = (const float*)d_in[5];
    const float* kb   = (const float*)d_in[6];
    const float* vw   = (const float*)d_in[7];
    const float* vs   = (const float*)d_in[8];
    const float* vb   = (const float*)d_in[9];
    const float* pw   = (const float*)d_in[10];
    const float* pwb  = (const float*)d_in[11];
    const float* ps   = (const float*)d_in[12];
    const float* psb  = (const float*)d_in[13];
    const float* f1w  = (const float*)d_in[14];
    const float* f1b  = (const float*)d_in[15];
    const float* f1s  = (const float*)d_in[16];
    const float* f1sb = (const float*)d_in[17];
    const float* f2w  = (const float*)d_in[18];
    const float* f2b  = (const float*)d_in[19];
    const float* f2s  = (const float*)d_in[20];
    const float* f2sb = (const float*)d_in[21];

    float *xt, *yb, *f2o, *wqkv, *wp, *wf1, *wf2, *attn;
    uint32_t *mq, *mkb, *mv;
    cudaGetSymbolAddress((void**)&xt,   g_xt);
    cudaGetSymbolAddress((void**)&yb,   g_y);
    cudaGetSymbolAddress((void**)&f2o,  g_f2);
    cudaGetSymbolAddress((void**)&wqkv, g_wqkv);
    cudaGetSymbolAddress((void**)&wp,   g_wp);
    cudaGetSymbolAddress((void**)&wf1,  g_wf1);
    cudaGetSymbolAddress((void**)&wf2,  g_wf2);
    cudaGetSymbolAddress((void**)&attn, g_attn);
    cudaGetSymbolAddress((void**)&mq,   g_mq);
    cudaGetSymbolAddress((void**)&mkb,  g_mk);
    cudaGetSymbolAddress((void**)&mv,   g_mv);

    float* out = (float*)d_out;
    int write_v = (out_size >= 2 * MAIN_ELEMS);
    float* vout = write_v ? (out + MAIN_ELEMS) : f2o;

    dim3 tb32(32, 8);
    qkvw_kern<<<dim3(CC / 32, CC / 32, 3), tb32>>>(qw, kw, vw, wqkv);
    tkern<<<dim3(CC / 32, CC / 32, 1), tb32>>>(pw,  wp,  CC,  CC);
    tkern<<<dim3(CC / 32, HID / 32, 1), tb32>>>(f1w, wf1, HID, CC);
    tkern<<<dim3(HID / 32, CC / 32, 1), tb32>>>(f2w, wf2, CC,  HID);

    // x -> [tb][v][c]
    tkern<<<dim3(VV / 32, CC / 32, NTB), tb32>>>(x, xt, CC, VV);

    // fused shortcut-LIF + qkv + qkv-LIF -> bitmasks (+ v float out)
    qkv_kernel<<<NBV, 256>>>(xt, wqkv, mq, mkb, mv, vout, write_v,
                             qs, qb, ks_, kb, vs, vb);

    // bit-domain attention
    attn1_kernel<<<128, 256>>>(mkb, mv, attn);
    attn2_kernel<<<dim3(32, 128), 256>>>(mq, attn, yb);

    // fused attn-LIF + proj + residual + MLP
    pmlp_kernel<<<NBV, 256>>>(yb, xt, wp, wf1, wf2,
                              pwb, ps, psb, f1b, f1s, f1sb, f2b, f2s, f2sb, f2o);

    // main output: transpose back to (T,B,C,V)
    tkern<<<dim3(CC / 32, VV / 32, NTB), tb32>>>(f2o, out, VV, CC);
}